// round 5
// baseline (speedup 1.0000x reference)
#include <cuda_runtime.h>
#include <math.h>

#define C 256
#define NPOS 32768
#define G 8
#define H 4

typedef unsigned long long u64;

// ---- scratch --------------------------------------------------------------
__device__ float g_tokens[2 * C * G];     // [b][c][g]
__device__ float g_Ms[2 * C * 32];        // [b][c][hg]  folded score matrix * nq_w
__device__ float g_P[2 * 32 * C];         // [b][hg][o]  folded output matrix
__device__ float g_cs[2 * 32];            // colsum of Ms*nq_w
__device__ float g_bias[2 * 32];          // Ms_raw . nq_b

// ---- f32x2 helpers ----------------------------------------------------------
__device__ __forceinline__ u64 dup2(float a) {
    u64 r; asm("mov.b64 %0,{%1,%1};" : "=l"(r) : "f"(a)); return r;
}
__device__ __forceinline__ u64 pack2(float a, float b) {
    u64 r; asm("mov.b64 %0,{%1,%2};" : "=l"(r) : "f"(a), "f"(b)); return r;
}
__device__ __forceinline__ u64 ffma2(u64 a, u64 b, u64 c) {
    u64 d; asm("fma.rn.f32x2 %0,%1,%2,%3;" : "=l"(d) : "l"(a), "l"(b), "l"(c)); return d;
}
__device__ __forceinline__ u64 add2(u64 a, u64 b) {
    u64 d; asm("add.rn.f32x2 %0,%1,%2;" : "=l"(d) : "l"(a), "l"(b)); return d;
}
__device__ __forceinline__ float lo2(u64 v) { return __uint_as_float((unsigned)v); }
__device__ __forceinline__ float hi2(u64 v) { return __uint_as_float((unsigned)(v >> 32)); }

__device__ __forceinline__ void cpa16(unsigned s, const void* g) {
    asm volatile("cp.async.cg.shared.global [%0], [%1], 16;" :: "r"(s), "l"(g));
}
__device__ __forceinline__ void cpa_commit() { asm volatile("cp.async.commit_group;"); }
__device__ __forceinline__ void cpa_wait1() { asm volatile("cp.async.wait_group 1;"); }
__device__ __forceinline__ void cpa_wait0() { asm volatile("cp.async.wait_group 0;"); }

// ---------------------------------------------------------------------------
// pool 16^3 -> 2^3 + depthwise 3^3 conv (SAME) + residual
// ---------------------------------------------------------------------------
__global__ void k_tokens(const float* __restrict__ x1,
                         const float* __restrict__ dw_w) {
    int bc = blockIdx.x;               // b*256 + c
    int c = bc & 255;
    const float* xp = x1 + (size_t)bc * 4096;
    int tid = threadIdx.x;
    int w = tid >> 5, lane = tid & 31;
    int gz = w >> 2, gy = (w >> 1) & 1, gx = w & 1;
    float s = 0.f;
#pragma unroll
    for (int k = 0; k < 16; k++) {
        int e = lane + 32 * k;
        int lz = e >> 6, ly = (e >> 3) & 7, lx = e & 7;
        s += xp[(gz * 8 + lz) * 256 + (gy * 8 + ly) * 16 + (gx * 8 + lx)];
    }
#pragma unroll
    for (int off = 16; off; off >>= 1) s += __shfl_down_sync(0xffffffffu, s, off);
    __shared__ float pooled[8];
    if (lane == 0) pooled[w] = s * (1.0f / 512.0f);
    __syncthreads();
    if (tid < 8) {
        int z = tid >> 2, y = (tid >> 1) & 1, x = tid & 1;
        float acc = 0.f;
        for (int dz = -1; dz <= 1; dz++)
            for (int dy = -1; dy <= 1; dy++)
                for (int dx = -1; dx <= 1; dx++) {
                    int nz = z + dz, ny = y + dy, nx = x + dx;
                    if ((unsigned)nz < 2u && (unsigned)ny < 2u && (unsigned)nx < 2u)
                        acc += dw_w[c * 27 + (dz + 1) * 9 + (dy + 1) * 3 + (dx + 1)] *
                               pooled[nz * 4 + ny * 2 + nx];
                }
        g_tokens[bc * 8 + tid] = pooled[tid] + acc;
    }
}

// ---------------------------------------------------------------------------
// Fused prep: LN(tokens) -> K,V (smem) -> Ms, P, cs, bias.   grid 16 = b*8+g
// ---------------------------------------------------------------------------
#define PP_PW 0                 /* 256*65 padded proj_w chunk */
#define PP_TOK (256 * 65)
#define PP_TK  (PP_TOK + 256)
#define PP_KD  (PP_TK + 256)
#define PP_VD  (PP_KD + 256)
#define PP_RED (PP_VD + 256)    /* 64 */
#define PP_TOT (PP_RED + 64)

__global__ void k_prep(const float* __restrict__ k_w, const float* __restrict__ v_w,
                       const float* __restrict__ q_w, const float* __restrict__ proj_w,
                       const float* __restrict__ nkv_w, const float* __restrict__ nkv_b,
                       const float* __restrict__ nq_w, const float* __restrict__ nq_b) {
    extern __shared__ float ps[];
    int bg = blockIdx.x;
    int b = bg >> 3, g = bg & 7;
    int tid = threadIdx.x;
    int w = tid >> 5, lane = tid & 31;
    __shared__ float red8[16];
    __shared__ float uu, rstd;

    // LN over channels of this token
    float t = g_tokens[(b * 256 + tid) * 8 + g];
    ps[PP_TOK + tid] = t;
    float s1 = t, s2 = t * t;
#pragma unroll
    for (int off = 16; off; off >>= 1) {
        s1 += __shfl_down_sync(0xffffffffu, s1, off);
        s2 += __shfl_down_sync(0xffffffffu, s2, off);
    }
    if (lane == 0) { red8[w] = s1; red8[8 + w] = s2; }
    __syncthreads();
    if (tid == 0) {
        float a = 0.f, q = 0.f;
        for (int i = 0; i < 8; i++) { a += red8[i]; q += red8[8 + i]; }
        float u = a * (1.0f / 256.0f);
        float var = q * (1.0f / 256.0f) - u * u;
        uu = u; rstd = rsqrtf(var + 1e-6f);
    }
    __syncthreads();
    ps[PP_TK + tid] = (t - uu) * rstd * nkv_w[tid] + nkv_b[tid];
    __syncthreads();

    // K, V into smem: warp w -> outputs o = w*32..w*32+31, lane-split over c
    for (int oo = 0; oo < 32; oo++) {
        int o = w * 32 + oo;
        const float* kr = k_w + o * 256;
        const float* vr = v_w + o * 256;
        float pk = 0.f, pv = 0.f;
#pragma unroll
        for (int i = 0; i < 8; i++) {
            int c2 = lane + 32 * i;
            pk += kr[c2] * ps[PP_TK + c2];
            pv += vr[c2] * ps[PP_TOK + c2];
        }
#pragma unroll
        for (int off = 16; off; off >>= 1) {
            pk += __shfl_down_sync(0xffffffffu, pk, off);
            pv += __shfl_down_sync(0xffffffffu, pv, off);
        }
        if (lane == 0) {
            ps[PP_KD + o] = pk * 0.125f;
            ps[PP_VD + o] = pv;
        }
    }
    __syncthreads();

    // Ms: thread = c; 4 heads
    float spv[4], sbv[4];
    {
        float nw = nq_w[tid], nb = nq_b[tid];
#pragma unroll
        for (int h = 0; h < 4; h++) {
            float s = 0.f;
            const float* qp = q_w + (h * 64) * 256 + tid;
#pragma unroll 8
            for (int d = 0; d < 64; d++) s += qp[d * 256] * ps[PP_KD + h * 64 + d];
            spv[h] = s * nw;
            sbv[h] = s * nb;
            g_Ms[(b * 256 + tid) * 32 + h * 8 + g] = spv[h];
        }
    }

    // P: chunk proj_w[:, h*64:(h+1)*64] through padded smem, then private dots
    for (int h = 0; h < 4; h++) {
        __syncthreads();
        for (int i = tid; i < 16384; i += 256) {
            int o = i >> 6, d = i & 63;
            ps[PP_PW + o * 65 + d] = proj_w[o * 256 + h * 64 + d];
        }
        __syncthreads();
        float p = 0.f;
        const float* pr = ps + PP_PW + tid * 65;
        const float* vd = ps + PP_VD + h * 64;
#pragma unroll 8
        for (int d = 0; d < 64; d++) p += pr[d] * vd[d];
        g_P[b * 8192 + (h * 8 + g) * 256 + tid] = p;
    }

    // cs / bias reduction per head
#pragma unroll
    for (int h = 0; h < 4; h++) {
        float a1 = spv[h], a2 = sbv[h];
#pragma unroll
        for (int off = 16; off; off >>= 1) {
            a1 += __shfl_down_sync(0xffffffffu, a1, off);
            a2 += __shfl_down_sync(0xffffffffu, a2, off);
        }
        if (lane == 0) {
            ps[PP_RED + h * 8 + w] = a1;
            ps[PP_RED + 32 + h * 8 + w] = a2;
        }
    }
    __syncthreads();
    if (tid < 4) {
        float c1 = 0.f, c2 = 0.f;
        for (int i = 0; i < 8; i++) {
            c1 += ps[PP_RED + tid * 8 + i];
            c2 += ps[PP_RED + 32 + tid * 8 + i];
        }
        g_cs[b * 32 + tid * 8 + g] = c1;
        g_bias[b * 32 + tid * 8 + g] = c2;
    }
}

// ---------------------------------------------------------------------------
// main fused kernel: 256 positions/block, 256 threads, 3 blocks/SM.
// X staging: 32 chunks of 8 channels, 3-stage cp.async ring, 1 sync/chunk.
// Weights time-multiplexed: Ms during GEMM1, P loaded after into same region.
// ---------------------------------------------------------------------------
#define SM_W   0              /* 8192: Ms, later P */
#define SM_XS  8192           /* 8192: X ring (3 x 2048) / S[32][256] after */
#define SM_RED 16384          /* 1024 (512 u64) */
#define SM_US  17408
#define SM_RS  17664
#define SM_CSB 17920          /* cs[32] bias[32] */
#define SM_TOT 17984

__global__ void __launch_bounds__(256, 3) k_main(
    const float* __restrict__ x2, float* __restrict__ out) {
    extern __shared__ float sm[];
    int tid = threadIdx.x;
    int j = tid & 127, og = tid >> 7;
    int b = blockIdx.x >> 7;
    int n0 = (blockIdx.x & 127) * 256;

    const float* xb = x2 + (size_t)b * C * NPOS + n0;
    unsigned xs_u32 = (unsigned)__cvta_generic_to_shared(sm + SM_XS);

    // prologue: chunks 0 and 1 (8 channels x 256 pos each)
#pragma unroll
    for (int pc = 0; pc < 2; pc++) {
        const float* src = xb + (size_t)(pc * 8) * NPOS;
        unsigned dst = xs_u32 + (unsigned)pc * 8192u;
#pragma unroll
        for (int it = 0; it < 2; it++) {
            int idx = tid + it * 256;
            int row = idx >> 6, col = idx & 63;
            cpa16(dst + (unsigned)(row * 1024 + col * 16),
                  src + (size_t)row * NPOS + col * 4);
        }
        cpa_commit();
    }

    // load Ms + cs/bias (L2-resident)
    for (int i = tid; i < 8192; i += 256) sm[SM_W + i] = g_Ms[b * 8192 + i];
    if (tid < 32) {
        sm[SM_CSB + tid]      = g_cs[b * 32 + tid];
        sm[SM_CSB + 32 + tid] = g_bias[b * 32 + tid];
    }

    u64 acc0[8], acc1[8], s1p = 0ull, s2p = 0ull;
#pragma unroll
    for (int k = 0; k < 8; k++) { acc0[k] = 0ull; acc1[k] = 0ull; }

    int buf = 0;   // ch % 3
    for (int ch = 0; ch < 32; ch++) {
        if (ch < 31) cpa_wait1(); else cpa_wait0();
        __syncthreads();
        if (ch + 2 < 32) {
            const float* src = xb + (size_t)((ch + 2) * 8) * NPOS;
            int nb = buf + 2; if (nb >= 3) nb -= 3;
            unsigned dst = xs_u32 + (unsigned)nb * 8192u;
#pragma unroll
            for (int it = 0; it < 2; it++) {
                int idx = tid + it * 256;
                int row = idx >> 6, col = idx & 63;
                cpa16(dst + (unsigned)(row * 1024 + col * 16),
                      src + (size_t)row * NPOS + col * 4);
            }
            cpa_commit();
        }

        const float* Xc = sm + SM_XS + buf * 2048;
        bool dostats = (og == (ch >> 4));
#pragma unroll
        for (int cl = 0; cl < 8; cl++) {
            float x0 = Xc[cl * 256 + j];
            float x1 = Xc[cl * 256 + j + 128];
            u64 x0d = dup2(x0), x1d = dup2(x1);
            const ulonglong2* wq = reinterpret_cast<const ulonglong2*>(
                sm + SM_W + (ch * 8 + cl) * 32 + og * 16);
#pragma unroll
            for (int pr = 0; pr < 4; pr++) {
                ulonglong2 wv = wq[pr];
                acc0[pr * 2]     = ffma2(wv.x, x0d, acc0[pr * 2]);
                acc0[pr * 2 + 1] = ffma2(wv.y, x0d, acc0[pr * 2 + 1]);
                acc1[pr * 2]     = ffma2(wv.x, x1d, acc1[pr * 2]);
                acc1[pr * 2 + 1] = ffma2(wv.y, x1d, acc1[pr * 2 + 1]);
            }
            if (dostats) {
                u64 xp = pack2(x0, x1);
                s1p = add2(s1p, xp);
                s2p = ffma2(xp, xp, s2p);
            }
        }
        buf++; if (buf == 3) buf = 0;
    }

    // ---- reduce LN stats
    u64* redm = reinterpret_cast<u64*>(sm + SM_RED);
    redm[(og * 128 + j) * 2]     = s1p;
    redm[(og * 128 + j) * 2 + 1] = s2p;
    __syncthreads();
    // load P into W region (Ms dead; all threads past compute)
    for (int i = tid; i < 8192; i += 256) sm[SM_W + i] = g_P[b * 8192 + i];
    if (og == 0) {
        u64 s1t = add2(redm[j * 2], redm[(128 + j) * 2]);
        u64 s2t = add2(redm[j * 2 + 1], redm[(128 + j) * 2 + 1]);
        float u0 = lo2(s1t) * (1.0f / 256.0f), u1 = hi2(s1t) * (1.0f / 256.0f);
        float v0 = lo2(s2t) * (1.0f / 256.0f) - u0 * u0;
        float v1 = hi2(s2t) * (1.0f / 256.0f) - u1 * u1;
        sm[SM_US + j] = u0;       sm[SM_US + j + 128] = u1;
        sm[SM_RS + j] = rsqrtf(v0 + 1e-6f);
        sm[SM_RS + j + 128] = rsqrtf(v1 + 1e-6f);
    }
    __syncthreads();

    // ---- correct scores, write S[hg][pos] (reuses X ring region)
    {
        u64 nu0 = dup2(-sm[SM_US + j]);
        u64 nu1 = dup2(-sm[SM_US + j + 128]);
        u64 r0  = dup2(sm[SM_RS + j]);
        u64 r1  = dup2(sm[SM_RS + j + 128]);
        const u64* csb = reinterpret_cast<const u64*>(sm + SM_CSB);
#pragma unroll
        for (int oo = 0; oo < 8; oo++) {
            int o = og * 16 + oo * 2;
            u64 cs2 = csb[o >> 1];
            u64 b2  = csb[16 + (o >> 1)];
            u64 sc0 = ffma2(ffma2(cs2, nu0, acc0[oo]), r0, b2);
            u64 sc1 = ffma2(ffma2(cs2, nu1, acc1[oo]), r1, b2);
            sm[SM_XS + o * 256 + j]             = lo2(sc0);
            sm[SM_XS + (o + 1) * 256 + j]       = hi2(sc0);
            sm[SM_XS + o * 256 + j + 128]       = lo2(sc1);
            sm[SM_XS + (o + 1) * 256 + j + 128] = hi2(sc1);
        }
    }
    __syncthreads();

    // ---- softmax: thread = position, 4 heads x 8 keys
    {
        int p = tid;
#pragma unroll
        for (int h = 0; h < 4; h++) {
            float v[8], m = -1e30f;
#pragma unroll
            for (int g = 0; g < 8; g++) {
                v[g] = sm[SM_XS + (h * 8 + g) * 256 + p];
                m = fmaxf(m, v[g]);
            }
            float ssum = 0.f;
#pragma unroll
            for (int g = 0; g < 8; g++) { v[g] = __expf(v[g] - m); ssum += v[g]; }
            float inv = 1.0f / ssum;
#pragma unroll
            for (int g = 0; g < 8; g++)
                sm[SM_XS + (h * 8 + g) * 256 + p] = v[g] * inv;
        }
    }
    __syncthreads();

    // ---- GEMM2: out[o][p] = sum_k A[k][p] * P[k][o]
    float* ob = out + (size_t)b * C * NPOS + n0;
    for (int oc = 0; oc < 8; oc++) {
        u64 c0[8], c1[8];
#pragma unroll
        for (int k = 0; k < 8; k++) { c0[k] = 0ull; c1[k] = 0ull; }
        int obase = oc * 32 + og * 16;
#pragma unroll 8
        for (int k = 0; k < 32; k++) {
            float a0 = sm[SM_XS + k * 256 + j];
            float a1 = sm[SM_XS + k * 256 + j + 128];
            u64 a0d = dup2(a0), a1d = dup2(a1);
            const ulonglong2* wq = reinterpret_cast<const ulonglong2*>(
                sm + SM_W + k * 256 + obase);
#pragma unroll
            for (int pr = 0; pr < 4; pr++) {
                ulonglong2 wv = wq[pr];
                c0[pr * 2]     = ffma2(wv.x, a0d, c0[pr * 2]);
                c0[pr * 2 + 1] = ffma2(wv.y, a0d, c0[pr * 2 + 1]);
                c1[pr * 2]     = ffma2(wv.x, a1d, c1[pr * 2]);
                c1[pr * 2 + 1] = ffma2(wv.y, a1d, c1[pr * 2 + 1]);
            }
        }
#pragma unroll
        for (int oo = 0; oo < 8; oo++) {
            int o = obase + oo * 2;
            ob[(size_t)o * NPOS + j]             = lo2(c0[oo]);
            ob[(size_t)(o + 1) * NPOS + j]       = hi2(c0[oo]);
            ob[(size_t)o * NPOS + j + 128]       = lo2(c1[oo]);
            ob[(size_t)(o + 1) * NPOS + j + 128] = hi2(c1[oo]);
        }
    }
}

// ---------------------------------------------------------------------------
extern "C" void kernel_launch(void* const* d_in, const int* in_sizes, int n_in,
                              void* d_out, int out_size) {
    const float* x2     = (const float*)d_in[0];
    const float* x1_low = (const float*)d_in[1];
    const float* q_w    = (const float*)d_in[2];
    const float* k_w    = (const float*)d_in[3];
    const float* v_w    = (const float*)d_in[4];
    const float* dw_w   = (const float*)d_in[5];
    const float* proj_w = (const float*)d_in[6];
    const float* nq_w   = (const float*)d_in[7];
    const float* nq_b   = (const float*)d_in[8];
    const float* nkv_w  = (const float*)d_in[9];
    const float* nkv_b  = (const float*)d_in[10];
    float* out = (float*)d_out;

    cudaFuncSetAttribute(k_prep, cudaFuncAttributeMaxDynamicSharedMemorySize,
                         PP_TOT * sizeof(float));
    cudaFuncSetAttribute(k_main, cudaFuncAttributeMaxDynamicSharedMemorySize,
                         SM_TOT * sizeof(float));

    k_tokens<<<512, 256>>>(x1_low, dw_w);
    k_prep<<<16, 256, PP_TOT * sizeof(float)>>>(k_w, v_w, q_w, proj_w,
                                                nkv_w, nkv_b, nq_w, nq_b);
    k_main<<<256, 256, SM_TOT * sizeof(float)>>>(x2, out);
}

// round 6
// speedup vs baseline: 1.0322x; 1.0322x over previous
#include <cuda_runtime.h>
#include <math.h>

#define C 256
#define NPOS 32768
#define G 8
#define H 4

typedef unsigned long long u64;

// ---- scratch --------------------------------------------------------------
__device__ float g_tokens[2 * C * G];     // [b][c][g]
__device__ float g_Ms[2 * C * 32];        // [b][c][hg]  folded score matrix * nq_w
__device__ float g_P[2 * 32 * C];         // [b][hg][o]  folded output matrix
__device__ float g_cs[2 * 32];            // colsum of Ms*nq_w
__device__ float g_bias[2 * 32];          // Ms_raw . nq_b

// ---- f32x2 helpers ----------------------------------------------------------
__device__ __forceinline__ u64 dup2(float a) {
    u64 r; asm("mov.b64 %0,{%1,%1};" : "=l"(r) : "f"(a)); return r;
}
__device__ __forceinline__ u64 pack2(float a, float b) {
    u64 r; asm("mov.b64 %0,{%1,%2};" : "=l"(r) : "f"(a), "f"(b)); return r;
}
__device__ __forceinline__ u64 ffma2(u64 a, u64 b, u64 c) {
    u64 d; asm("fma.rn.f32x2 %0,%1,%2,%3;" : "=l"(d) : "l"(a), "l"(b), "l"(c)); return d;
}
__device__ __forceinline__ u64 add2(u64 a, u64 b) {
    u64 d; asm("add.rn.f32x2 %0,%1,%2;" : "=l"(d) : "l"(a), "l"(b)); return d;
}
__device__ __forceinline__ float lo2(u64 v) { return __uint_as_float((unsigned)v); }
__device__ __forceinline__ float hi2(u64 v) { return __uint_as_float((unsigned)(v >> 32)); }

__device__ __forceinline__ void cpa16(unsigned s, const void* g) {
    asm volatile("cp.async.cg.shared.global [%0], [%1], 16;" :: "r"(s), "l"(g));
}
__device__ __forceinline__ void cpa_commit() { asm volatile("cp.async.commit_group;"); }
__device__ __forceinline__ void cpa_wait1() { asm volatile("cp.async.wait_group 1;"); }
__device__ __forceinline__ void cpa_wait0() { asm volatile("cp.async.wait_group 0;"); }

// ---------------------------------------------------------------------------
// pool 16^3 -> 2^3 + depthwise 3^3 conv (SAME) + residual — vectorized loads
// ---------------------------------------------------------------------------
__global__ void k_tokens(const float* __restrict__ x1,
                         const float* __restrict__ dw_w) {
    int bc = blockIdx.x;               // b*256 + c
    int c = bc & 255;
    const float* xp = x1 + (size_t)bc * 4096;
    int tid = threadIdx.x;
    int w = tid >> 5, lane = tid & 31;
    int gz = w >> 2, gy = (w >> 1) & 1, gx = w & 1;
    float s = 0.f;
#pragma unroll
    for (int p = 0; p < 2; p++) {
        int idx = lane + p * 32;       // 0..63 -> (lz,ly)
        int lz = idx >> 3, ly = idx & 7;
        const float4* r = reinterpret_cast<const float4*>(
            xp + (gz * 8 + lz) * 256 + (gy * 8 + ly) * 16 + gx * 8);
        float4 a = r[0], b4 = r[1];
        s += a.x + a.y + a.z + a.w + b4.x + b4.y + b4.z + b4.w;
    }
#pragma unroll
    for (int off = 16; off; off >>= 1) s += __shfl_down_sync(0xffffffffu, s, off);
    __shared__ float pooled[8];
    if (lane == 0) pooled[w] = s * (1.0f / 512.0f);
    __syncthreads();
    if (tid < 8) {
        int z = tid >> 2, y = (tid >> 1) & 1, x = tid & 1;
        float acc = 0.f;
        for (int dz = -1; dz <= 1; dz++)
            for (int dy = -1; dy <= 1; dy++)
                for (int dx = -1; dx <= 1; dx++) {
                    int nz = z + dz, ny = y + dy, nx = x + dx;
                    if ((unsigned)nz < 2u && (unsigned)ny < 2u && (unsigned)nx < 2u)
                        acc += dw_w[c * 27 + (dz + 1) * 9 + (dy + 1) * 3 + (dx + 1)] *
                               pooled[nz * 4 + ny * 2 + nx];
                }
        g_tokens[bc * 8 + tid] = pooled[tid] + acc;
    }
}

// ---------------------------------------------------------------------------
// Fused prep: LN(tokens) -> K,V (smem) -> Ms, P, cs, bias.   grid 16 = b*8+g
// ---------------------------------------------------------------------------
#define PP_PW 0                 /* 256*65 padded proj_w chunk */
#define PP_TOK (256 * 65)
#define PP_TK  (PP_TOK + 256)
#define PP_KD  (PP_TK + 256)
#define PP_VD  (PP_KD + 256)
#define PP_RED (PP_VD + 256)    /* 64 */
#define PP_TOT (PP_RED + 64)

__global__ void k_prep(const float* __restrict__ k_w, const float* __restrict__ v_w,
                       const float* __restrict__ q_w, const float* __restrict__ proj_w,
                       const float* __restrict__ nkv_w, const float* __restrict__ nkv_b,
                       const float* __restrict__ nq_w, const float* __restrict__ nq_b) {
    extern __shared__ float ps[];
    int bg = blockIdx.x;
    int b = bg >> 3, g = bg & 7;
    int tid = threadIdx.x;
    int w = tid >> 5, lane = tid & 31;
    __shared__ float red8[16];
    __shared__ float uu, rstd;

    // LN over channels of this token
    float t = g_tokens[(b * 256 + tid) * 8 + g];
    ps[PP_TOK + tid] = t;
    float s1 = t, s2 = t * t;
#pragma unroll
    for (int off = 16; off; off >>= 1) {
        s1 += __shfl_down_sync(0xffffffffu, s1, off);
        s2 += __shfl_down_sync(0xffffffffu, s2, off);
    }
    if (lane == 0) { red8[w] = s1; red8[8 + w] = s2; }
    __syncthreads();
    if (tid == 0) {
        float a = 0.f, q = 0.f;
        for (int i = 0; i < 8; i++) { a += red8[i]; q += red8[8 + i]; }
        float u = a * (1.0f / 256.0f);
        float var = q * (1.0f / 256.0f) - u * u;
        uu = u; rstd = rsqrtf(var + 1e-6f);
    }
    __syncthreads();
    ps[PP_TK + tid] = (t - uu) * rstd * nkv_w[tid] + nkv_b[tid];
    __syncthreads();

    // K, V into smem: warp w -> outputs o = w*32..w*32+31, lane-split over c
    for (int oo = 0; oo < 32; oo++) {
        int o = w * 32 + oo;
        const float* kr = k_w + o * 256;
        const float* vr = v_w + o * 256;
        float pk = 0.f, pv = 0.f;
#pragma unroll
        for (int i = 0; i < 8; i++) {
            int c2 = lane + 32 * i;
            pk += kr[c2] * ps[PP_TK + c2];
            pv += vr[c2] * ps[PP_TOK + c2];
        }
#pragma unroll
        for (int off = 16; off; off >>= 1) {
            pk += __shfl_down_sync(0xffffffffu, pk, off);
            pv += __shfl_down_sync(0xffffffffu, pv, off);
        }
        if (lane == 0) {
            ps[PP_KD + o] = pk * 0.125f;
            ps[PP_VD + o] = pv;
        }
    }
    __syncthreads();

    // Ms: thread = c; 4 heads
    float spv[4], sbv[4];
    {
        float nw = nq_w[tid], nb = nq_b[tid];
#pragma unroll
        for (int h = 0; h < 4; h++) {
            float s = 0.f;
            const float* qp = q_w + (h * 64) * 256 + tid;
#pragma unroll 8
            for (int d = 0; d < 64; d++) s += qp[d * 256] * ps[PP_KD + h * 64 + d];
            spv[h] = s * nw;
            sbv[h] = s * nb;
            g_Ms[(b * 256 + tid) * 32 + h * 8 + g] = spv[h];
        }
    }

    // P: chunk proj_w[:, h*64:(h+1)*64] through padded smem, then private dots
    for (int h = 0; h < 4; h++) {
        __syncthreads();
        for (int i = tid; i < 16384; i += 256) {
            int o = i >> 6, d = i & 63;
            ps[PP_PW + o * 65 + d] = proj_w[o * 256 + h * 64 + d];
        }
        __syncthreads();
        float p = 0.f;
        const float* pr = ps + PP_PW + tid * 65;
        const float* vd = ps + PP_VD + h * 64;
#pragma unroll 8
        for (int d = 0; d < 64; d++) p += pr[d] * vd[d];
        g_P[b * 8192 + (h * 8 + g) * 256 + tid] = p;
    }

    // cs / bias reduction per head
#pragma unroll
    for (int h = 0; h < 4; h++) {
        float a1 = spv[h], a2 = sbv[h];
#pragma unroll
        for (int off = 16; off; off >>= 1) {
            a1 += __shfl_down_sync(0xffffffffu, a1, off);
            a2 += __shfl_down_sync(0xffffffffu, a2, off);
        }
        if (lane == 0) {
            ps[PP_RED + h * 8 + w] = a1;
            ps[PP_RED + 32 + h * 8 + w] = a2;
        }
    }
    __syncthreads();
    if (tid < 4) {
        float c1 = 0.f, c2 = 0.f;
        for (int i = 0; i < 8; i++) {
            c1 += ps[PP_RED + tid * 8 + i];
            c2 += ps[PP_RED + 32 + tid * 8 + i];
        }
        g_cs[b * 32 + tid * 8 + g] = c1;
        g_bias[b * 32 + tid * 8 + g] = c2;
    }
}

// ---------------------------------------------------------------------------
// main fused kernel (round-4 proven structure): 256 positions/block,
// 16 chunks x 16 channels, 2-stage double buffer, 2 blocks/SM.
// ---------------------------------------------------------------------------
#define SM_MSP 0
#define SM_P   8192
#define SM_X   16384          /* 2 bufs x 4096 floats; also S[32][256] after GEMM1 */
#define SM_S   16384
#define SM_RED 24576          /* 512 u64 */
#define SM_US  25600
#define SM_RS  25856
#define SM_CSB 26112          /* cs[32] bias[32] */
#define SM_TOT 26176

__global__ void __launch_bounds__(256, 2) k_main(
    const float* __restrict__ x2, float* __restrict__ out) {
    extern __shared__ float sm[];
    int tid = threadIdx.x;
    int j = tid & 127, og = tid >> 7;
    int b = blockIdx.x >> 7;
    int n0 = (blockIdx.x & 127) * 256;

    const float* xb = x2 + (size_t)b * C * NPOS + n0;
    unsigned xs_u32 = (unsigned)__cvta_generic_to_shared(sm + SM_X);

    // prologue: chunk 0 (16 channels x 256 pos)
    {
#pragma unroll
        for (int it = 0; it < 4; it++) {
            int idx = tid + it * 256;
            int row = idx >> 6, col = idx & 63;
            cpa16(xs_u32 + (unsigned)(row * 1024 + col * 16),
                  xb + (size_t)row * NPOS + col * 4);
        }
        cpa_commit();
    }

    // load folded weights (L2-resident, shared across blocks)
    for (int i = tid; i < 8192; i += 256) {
        sm[SM_MSP + i] = g_Ms[b * 8192 + i];
        sm[SM_P + i]   = g_P[b * 8192 + i];
    }
    if (tid < 32) {
        sm[SM_CSB + tid]      = g_cs[b * 32 + tid];
        sm[SM_CSB + 32 + tid] = g_bias[b * 32 + tid];
    }

    u64 acc0[8], acc1[8], s1p = 0ull, s2p = 0ull;
#pragma unroll
    for (int k = 0; k < 8; k++) { acc0[k] = 0ull; acc1[k] = 0ull; }

    for (int ch = 0; ch < 16; ch++) {
        if (ch < 15) {
            const float* src = xb + (size_t)((ch + 1) * 16) * NPOS;
            unsigned dst = xs_u32 + ((unsigned)((ch + 1) & 1)) * 16384u;
#pragma unroll
            for (int it = 0; it < 4; it++) {
                int idx = tid + it * 256;
                int row = idx >> 6, col = idx & 63;
                cpa16(dst + (unsigned)(row * 1024 + col * 16),
                      src + (size_t)row * NPOS + col * 4);
            }
            cpa_commit();
            cpa_wait1();
        } else {
            cpa_wait0();
        }
        __syncthreads();

        const float* Xc = sm + SM_X + ((ch & 1) << 12);
        bool dostats = (og == (ch >> 3));
#pragma unroll
        for (int cl = 0; cl < 16; cl++) {
            float x0 = Xc[cl * 256 + j];
            float x1 = Xc[cl * 256 + j + 128];
            u64 x0d = dup2(x0), x1d = dup2(x1);
            const ulonglong2* wq = reinterpret_cast<const ulonglong2*>(
                sm + SM_MSP + (ch * 16 + cl) * 32 + og * 16);
#pragma unroll
            for (int pr = 0; pr < 4; pr++) {
                ulonglong2 w = wq[pr];
                acc0[pr * 2]     = ffma2(w.x, x0d, acc0[pr * 2]);
                acc0[pr * 2 + 1] = ffma2(w.y, x0d, acc0[pr * 2 + 1]);
                acc1[pr * 2]     = ffma2(w.x, x1d, acc1[pr * 2]);
                acc1[pr * 2 + 1] = ffma2(w.y, x1d, acc1[pr * 2 + 1]);
            }
            if (dostats) {
                u64 xp = pack2(x0, x1);
                s1p = add2(s1p, xp);
                s2p = ffma2(xp, xp, s2p);
            }
        }
        __syncthreads();
    }

    // ---- reduce LN stats (pos j in lo lane, pos j+128 in hi lane)
    u64* redm = reinterpret_cast<u64*>(sm + SM_RED);
    redm[(og * 128 + j) * 2]     = s1p;
    redm[(og * 128 + j) * 2 + 1] = s2p;
    __syncthreads();
    if (og == 0) {
        u64 s1t = add2(redm[j * 2], redm[(128 + j) * 2]);
        u64 s2t = add2(redm[j * 2 + 1], redm[(128 + j) * 2 + 1]);
        float u0 = lo2(s1t) * (1.0f / 256.0f), u1 = hi2(s1t) * (1.0f / 256.0f);
        float v0 = lo2(s2t) * (1.0f / 256.0f) - u0 * u0;
        float v1 = hi2(s2t) * (1.0f / 256.0f) - u1 * u1;
        sm[SM_US + j] = u0;       sm[SM_US + j + 128] = u1;
        sm[SM_RS + j] = rsqrtf(v0 + 1e-6f);
        sm[SM_RS + j + 128] = rsqrtf(v1 + 1e-6f);
    }
    __syncthreads();

    // ---- correct scores, write S[hg][pos] (reuses X region)
    {
        u64 nu0 = dup2(-sm[SM_US + j]);
        u64 nu1 = dup2(-sm[SM_US + j + 128]);
        u64 r0  = dup2(sm[SM_RS + j]);
        u64 r1  = dup2(sm[SM_RS + j + 128]);
        const u64* csb = reinterpret_cast<const u64*>(sm + SM_CSB);
#pragma unroll
        for (int oo = 0; oo < 8; oo++) {
            int o = og * 16 + oo * 2;
            u64 cs2 = csb[o >> 1];
            u64 b2  = csb[16 + (o >> 1)];
            u64 sc0 = ffma2(ffma2(cs2, nu0, acc0[oo]), r0, b2);
            u64 sc1 = ffma2(ffma2(cs2, nu1, acc1[oo]), r1, b2);
            sm[SM_S + o * 256 + j]             = lo2(sc0);
            sm[SM_S + (o + 1) * 256 + j]       = hi2(sc0);
            sm[SM_S + o * 256 + j + 128]       = lo2(sc1);
            sm[SM_S + (o + 1) * 256 + j + 128] = hi2(sc1);
        }
    }
    __syncthreads();

    // ---- softmax: thread = position, 4 heads x 8 keys
    {
        int p = tid;
#pragma unroll
        for (int h = 0; h < 4; h++) {
            float v[8], m = -1e30f;
#pragma unroll
            for (int g = 0; g < 8; g++) {
                v[g] = sm[SM_S + (h * 8 + g) * 256 + p];
                m = fmaxf(m, v[g]);
            }
            float ssum = 0.f;
#pragma unroll
            for (int g = 0; g < 8; g++) { v[g] = __expf(v[g] - m); ssum += v[g]; }
            float inv = 1.0f / ssum;
#pragma unroll
            for (int g = 0; g < 8; g++)
                sm[SM_S + (h * 8 + g) * 256 + p] = v[g] * inv;
        }
    }
    __syncthreads();

    // ---- GEMM2: out[o][p] = sum_k A[k][p] * P[k][o]
    float* ob = out + (size_t)b * C * NPOS + n0;
    for (int oc = 0; oc < 8; oc++) {
        u64 c0[8], c1[8];
#pragma unroll
        for (int k = 0; k < 8; k++) { c0[k] = 0ull; c1[k] = 0ull; }
        int obase = oc * 32 + og * 16;
#pragma unroll 8
        for (int k = 0; k < 32; k++) {
            float a0 = sm[SM_S + k * 256 + j];
            float a1 = sm[SM_S + k * 256 + j + 128];
            u64 a0d = dup2(a0), a1d = dup2(a1);
            const ulonglong2* wq = reinterpret_cast<const ulonglong2*>(
                sm + SM_P + k * 256 + obase);
#pragma unroll
            for (int pr = 0; pr < 4; pr++) {
                ulonglong2 w = wq[pr];
                c0[pr * 2]     = ffma2(w.x, a0d, c0[pr * 2]);
                c0[pr * 2 + 1] = ffma2(w.y, a0d, c0[pr * 2 + 1]);
                c1[pr * 2]     = ffma2(w.x, a1d, c1[pr * 2]);
                c1[pr * 2 + 1] = ffma2(w.y, a1d, c1[pr * 2 + 1]);
            }
        }
#pragma unroll
        for (int oo = 0; oo < 8; oo++) {
            int o = obase + oo * 2;
            ob[(size_t)o * NPOS + j]             = lo2(c0[oo]);
            ob[(size_t)(o + 1) * NPOS + j]       = hi2(c0[oo]);
            ob[(size_t)o * NPOS + j + 128]       = lo2(c1[oo]);
            ob[(size_t)(o + 1) * NPOS + j + 128] = hi2(c1[oo]);
        }
    }
}

// ---------------------------------------------------------------------------
extern "C" void kernel_launch(void* const* d_in, const int* in_sizes, int n_in,
                              void* d_out, int out_size) {
    const float* x2     = (const float*)d_in[0];
    const float* x1_low = (const float*)d_in[1];
    const float* q_w    = (const float*)d_in[2];
    const float* k_w    = (const float*)d_in[3];
    const float* v_w    = (const float*)d_in[4];
    const float* dw_w   = (const float*)d_in[5];
    const float* proj_w = (const float*)d_in[6];
    const float* nq_w   = (const float*)d_in[7];
    const float* nq_b   = (const float*)d_in[8];
    const float* nkv_w  = (const float*)d_in[9];
    const float* nkv_b  = (const float*)d_in[10];
    float* out = (float*)d_out;

    cudaFuncSetAttribute(k_prep, cudaFuncAttributeMaxDynamicSharedMemorySize,
                         PP_TOT * sizeof(float));
    cudaFuncSetAttribute(k_main, cudaFuncAttributeMaxDynamicSharedMemorySize,
                         SM_TOT * sizeof(float));

    k_tokens<<<512, 256>>>(x1_low, dw_w);
    k_prep<<<16, 256, PP_TOT * sizeof(float)>>>(k_w, v_w, q_w, proj_w,
                                                nkv_w, nkv_b, nq_w, nq_b);
    k_main<<<256, 256, SM_TOT * sizeof(float)>>>(x2, out);
}

// round 7
// speedup vs baseline: 1.2687x; 1.2291x over previous
#include <cuda_runtime.h>
#include <math.h>

#define C 256
#define NPOS 32768
#define G 8
#define H 4

typedef unsigned long long u64;

// ---- scratch --------------------------------------------------------------
__device__ float g_tokens[2 * C * G];     // [b][c][g]
__device__ float g_K[2 * H * 64 * G];     // [b][h][d][g], pre-scaled by 1/8
__device__ float g_V[2 * H * G * 64];     // [b][h][g][d]
__device__ float g_Ms[2 * C * 32];        // [b][c][hg]  folded score matrix * nq_w
__device__ float g_P[2 * 32 * C];         // [b][hg][o]  folded output matrix
__device__ float g_cs[2 * 32];            // colsum of Ms*nq_w
__device__ float g_bias[2 * 32];          // Ms_raw . nq_b

// ---- f32x2 helpers ----------------------------------------------------------
__device__ __forceinline__ u64 dup2(float a) {
    u64 r; asm("mov.b64 %0,{%1,%1};" : "=l"(r) : "f"(a)); return r;
}
__device__ __forceinline__ u64 pack2(float a, float b) {
    u64 r; asm("mov.b64 %0,{%1,%2};" : "=l"(r) : "f"(a), "f"(b)); return r;
}
__device__ __forceinline__ u64 ffma2(u64 a, u64 b, u64 c) {
    u64 d; asm("fma.rn.f32x2 %0,%1,%2,%3;" : "=l"(d) : "l"(a), "l"(b), "l"(c)); return d;
}
__device__ __forceinline__ u64 add2(u64 a, u64 b) {
    u64 d; asm("add.rn.f32x2 %0,%1,%2;" : "=l"(d) : "l"(a), "l"(b)); return d;
}
__device__ __forceinline__ float lo2(u64 v) { return __uint_as_float((unsigned)v); }
__device__ __forceinline__ float hi2(u64 v) { return __uint_as_float((unsigned)(v >> 32)); }

__device__ __forceinline__ void cpa16(unsigned s, const void* g) {
    asm volatile("cp.async.cg.shared.global [%0], [%1], 16;" :: "r"(s), "l"(g));
}
__device__ __forceinline__ void cpa_commit() { asm volatile("cp.async.commit_group;"); }
__device__ __forceinline__ void cpa_wait1() { asm volatile("cp.async.wait_group 1;"); }
__device__ __forceinline__ void cpa_wait0() { asm volatile("cp.async.wait_group 0;"); }

// ---------------------------------------------------------------------------
// pool 16^3 -> 2^3 + depthwise 3^3 conv (SAME) + residual — vectorized loads
// ---------------------------------------------------------------------------
__global__ void k_tokens(const float* __restrict__ x1,
                         const float* __restrict__ dw_w) {
    int bc = blockIdx.x;               // b*256 + c
    int c = bc & 255;
    const float* xp = x1 + (size_t)bc * 4096;
    int tid = threadIdx.x;
    int w = tid >> 5, lane = tid & 31;
    int gz = w >> 2, gy = (w >> 1) & 1, gx = w & 1;
    float s = 0.f;
#pragma unroll
    for (int p = 0; p < 2; p++) {
        int idx = lane + p * 32;       // 0..63 -> (lz,ly)
        int lz = idx >> 3, ly = idx & 7;
        const float4* r = reinterpret_cast<const float4*>(
            xp + (gz * 8 + lz) * 256 + (gy * 8 + ly) * 16 + gx * 8);
        float4 a = r[0], b4 = r[1];
        s += a.x + a.y + a.z + a.w + b4.x + b4.y + b4.z + b4.w;
    }
#pragma unroll
    for (int off = 16; off; off >>= 1) s += __shfl_down_sync(0xffffffffu, s, off);
    __shared__ float pooled[8];
    if (lane == 0) pooled[w] = s * (1.0f / 512.0f);
    __syncthreads();
    if (tid < 8) {
        int z = tid >> 2, y = (tid >> 1) & 1, x = tid & 1;
        float acc = 0.f;
        for (int dz = -1; dz <= 1; dz++)
            for (int dy = -1; dy <= 1; dy++)
                for (int dx = -1; dx <= 1; dx++) {
                    int nz = z + dz, ny = y + dy, nx = x + dx;
                    if ((unsigned)nz < 2u && (unsigned)ny < 2u && (unsigned)nx < 2u)
                        acc += dw_w[c * 27 + (dz + 1) * 9 + (dy + 1) * 3 + (dx + 1)] *
                               pooled[nz * 4 + ny * 2 + nx];
                }
        g_tokens[bc * 8 + tid] = pooled[tid] + acc;
    }
}

// ---------------------------------------------------------------------------
// LN(tokens) over channels, K (prescaled), V — round-4 proven
// ---------------------------------------------------------------------------
__global__ void k_kv(const float* __restrict__ k_w, const float* __restrict__ v_w,
                     const float* __restrict__ nkv_w, const float* __restrict__ nkv_b) {
    int bg = blockIdx.x;               // b*8 + g
    int b = bg >> 3, g = bg & 7;
    int tid = threadIdx.x;             // 256
    int w = tid >> 5, lane = tid & 31;
    __shared__ float tok[256], tk[256], red[16];
    __shared__ float uu, rstd;
    float t = g_tokens[(b * 256 + tid) * 8 + g];
    tok[tid] = t;
    float s1 = t, s2 = t * t;
#pragma unroll
    for (int off = 16; off; off >>= 1) {
        s1 += __shfl_down_sync(0xffffffffu, s1, off);
        s2 += __shfl_down_sync(0xffffffffu, s2, off);
    }
    if (lane == 0) { red[w] = s1; red[8 + w] = s2; }
    __syncthreads();
    if (tid == 0) {
        float a = 0.f, q = 0.f;
        for (int i = 0; i < 8; i++) { a += red[i]; q += red[8 + i]; }
        float u = a * (1.0f / 256.0f);
        float var = q * (1.0f / 256.0f) - u * u;
        uu = u; rstd = rsqrtf(var + 1e-6f);
    }
    __syncthreads();
    tk[tid] = (t - uu) * rstd * nkv_w[tid] + nkv_b[tid];
    __syncthreads();

    for (int oo = 0; oo < 32; oo++) {
        int o = w * 32 + oo;
        const float* kr = k_w + o * 256;
        const float* vr = v_w + o * 256;
        float pk = 0.f, pv = 0.f;
#pragma unroll
        for (int i = 0; i < 8; i++) {
            int c2 = lane + 32 * i;
            pk += kr[c2] * tk[c2];
            pv += vr[c2] * tok[c2];
        }
#pragma unroll
        for (int off = 16; off; off >>= 1) {
            pk += __shfl_down_sync(0xffffffffu, pk, off);
            pv += __shfl_down_sync(0xffffffffu, pv, off);
        }
        if (lane == 0) {
            int h = o >> 6, d = o & 63;
            g_K[((b * 4 + h) * 64 + d) * 8 + g] = pk * 0.125f;
            g_V[((b * 4 + h) * 8 + g) * 64 + d] = pv;
        }
    }
}

// ---------------------------------------------------------------------------
// foldA: Ms premul by nq_w, plus cs/bias. grid 64 = (b,hg), thread = c
// ---------------------------------------------------------------------------
__global__ void k_foldA(const float* __restrict__ q_w,
                        const float* __restrict__ nq_w,
                        const float* __restrict__ nq_b) {
    int bhg = blockIdx.x;
    int b = bhg >> 5, hg = bhg & 31, h = hg >> 3, g = hg & 7;
    int t = threadIdx.x;
    __shared__ float kd[64];
    __shared__ float r1[8], r2[8];
    if (t < 64) kd[t] = g_K[((b * 4 + h) * 64 + t) * 8 + g];
    __syncthreads();
    float s = 0.f;
    const float* qp = q_w + (h * 64) * 256 + t;
#pragma unroll 8
    for (int d = 0; d < 64; d++) s += qp[d * 256] * kd[d];
    float sp = s * nq_w[t];
    float sb = s * nq_b[t];
    g_Ms[(b * 256 + t) * 32 + hg] = sp;
    float a1 = sp, a2 = sb;
#pragma unroll
    for (int off = 16; off; off >>= 1) {
        a1 += __shfl_down_sync(0xffffffffu, a1, off);
        a2 += __shfl_down_sync(0xffffffffu, a2, off);
    }
    int w = t >> 5, lane = t & 31;
    if (lane == 0) { r1[w] = a1; r2[w] = a2; }
    __syncthreads();
    if (t == 0) {
        float c1 = 0.f, c2 = 0.f;
        for (int i = 0; i < 8; i++) { c1 += r1[i]; c2 += r2[i]; }
        g_cs[b * 32 + hg] = c1;
        g_bias[b * 32 + hg] = c2;
    }
}

// ---------------------------------------------------------------------------
// foldB: P[hg][o] = sum_d proj_w[o, h*64+d] * V[h,g,d]
// grid 256 = (b,hg,quarter); warp-per-output-row, 8 rows/warp
// ---------------------------------------------------------------------------
__global__ void k_foldB(const float* __restrict__ proj_w) {
    int bid = blockIdx.x;              // (b*32+hg)*4 + q
    int q = bid & 3;
    int bhg = bid >> 2;
    int b = bhg >> 5, hg = bhg & 31, h = hg >> 3, g = hg & 7;
    int tid = threadIdx.x;
    int w = tid >> 5, lane = tid & 31;
    __shared__ float vd[64];
    if (tid < 64) vd[tid] = g_V[((b * 4 + h) * 8 + g) * 64 + tid];
    __syncthreads();
#pragma unroll
    for (int oo = 0; oo < 8; oo++) {
        int o = q * 64 + w * 8 + oo;
        const float* pw = proj_w + o * 256 + h * 64;
        float p = pw[lane] * vd[lane] + pw[32 + lane] * vd[32 + lane];
#pragma unroll
        for (int off = 16; off; off >>= 1)
            p += __shfl_down_sync(0xffffffffu, p, off);
        if (lane == 0) g_P[b * 8192 + hg * 256 + o] = p;
    }
}

// ---------------------------------------------------------------------------
// main fused kernel: 256 positions/block, 16 chunks x 16 channels,
// ring-3 cp.async (depth 2), ONE sync per chunk, P time-muxed after GEMM1.
// smem 88 KB -> 2 blocks/SM.
// ---------------------------------------------------------------------------
#define SM_W   0              /* 8192: Ms, later P */
#define SM_X   8192           /* 3 x 4096 ring; S[32][256] after GEMM1 */
#define SM_S   8192
#define SM_RED 20480          /* 512 u64 = 1024 floats */
#define SM_US  21504
#define SM_RS  21760
#define SM_CSB 22016          /* cs[32] bias[32] */
#define SM_TOT 22080

__global__ void __launch_bounds__(256, 2) k_main(
    const float* __restrict__ x2, float* __restrict__ out) {
    extern __shared__ float sm[];
    int tid = threadIdx.x;
    int j = tid & 127, og = tid >> 7;
    int b = blockIdx.x >> 7;
    int n0 = (blockIdx.x & 127) * 256;

    const float* xb = x2 + (size_t)b * C * NPOS + n0;
    unsigned xs_u32 = (unsigned)__cvta_generic_to_shared(sm + SM_X);

    // prologue: chunks 0,1 into bufs 0,1
#pragma unroll
    for (int pc = 0; pc < 2; pc++) {
        const float* src = xb + (size_t)(pc * 16) * NPOS;
        unsigned dst = xs_u32 + (unsigned)pc * 16384u;
#pragma unroll
        for (int it = 0; it < 4; it++) {
            int idx = tid + it * 256;
            int row = idx >> 6, col = idx & 63;
            cpa16(dst + (unsigned)(row * 1024 + col * 16),
                  src + (size_t)row * NPOS + col * 4);
        }
        cpa_commit();
    }

    // Ms + cs/bias
    for (int i = tid; i < 8192; i += 256) sm[SM_W + i] = g_Ms[b * 8192 + i];
    if (tid < 32) {
        sm[SM_CSB + tid]      = g_cs[b * 32 + tid];
        sm[SM_CSB + 32 + tid] = g_bias[b * 32 + tid];
    }

    u64 acc0[8], acc1[8], s1p = 0ull, s2p = 0ull;
#pragma unroll
    for (int k = 0; k < 8; k++) { acc0[k] = 0ull; acc1[k] = 0ull; }

    int buf = 0;
    for (int ch = 0; ch < 16; ch++) {
        if (ch < 15) cpa_wait1(); else cpa_wait0();
        __syncthreads();                       // all warps done with buf (ch-1)%3
        if (ch + 2 < 16) {
            const float* src = xb + (size_t)((ch + 2) * 16) * NPOS;
            int nb = buf + 2; if (nb >= 3) nb -= 3;
            unsigned dst = xs_u32 + (unsigned)nb * 16384u;
#pragma unroll
            for (int it = 0; it < 4; it++) {
                int idx = tid + it * 256;
                int row = idx >> 6, col = idx & 63;
                cpa16(dst + (unsigned)(row * 1024 + col * 16),
                      src + (size_t)row * NPOS + col * 4);
            }
            cpa_commit();
        }

        const float* Xc = sm + SM_X + buf * 4096;
        bool dostats = (og == (ch >> 3));
#pragma unroll
        for (int cl = 0; cl < 16; cl++) {
            float x0 = Xc[cl * 256 + j];
            float x1 = Xc[cl * 256 + j + 128];
            u64 x0d = dup2(x0), x1d = dup2(x1);
            const ulonglong2* wq = reinterpret_cast<const ulonglong2*>(
                sm + SM_W + (ch * 16 + cl) * 32 + og * 16);
#pragma unroll
            for (int pr = 0; pr < 4; pr++) {
                ulonglong2 wv = wq[pr];
                acc0[pr * 2]     = ffma2(wv.x, x0d, acc0[pr * 2]);
                acc0[pr * 2 + 1] = ffma2(wv.y, x0d, acc0[pr * 2 + 1]);
                acc1[pr * 2]     = ffma2(wv.x, x1d, acc1[pr * 2]);
                acc1[pr * 2 + 1] = ffma2(wv.y, x1d, acc1[pr * 2 + 1]);
            }
            if (dostats) {
                u64 xp = pack2(x0, x1);
                s1p = add2(s1p, xp);
                s2p = ffma2(xp, xp, s2p);
            }
        }
        buf++; if (buf == 3) buf = 0;
    }

    // ---- reduce LN stats; load P into W region (Ms dead)
    u64* redm = reinterpret_cast<u64*>(sm + SM_RED);
    redm[(og * 128 + j) * 2]     = s1p;
    redm[(og * 128 + j) * 2 + 1] = s2p;
    __syncthreads();
    for (int i = tid; i < 8192; i += 256) sm[SM_W + i] = g_P[b * 8192 + i];
    if (og == 0) {
        u64 s1t = add2(redm[j * 2], redm[(128 + j) * 2]);
        u64 s2t = add2(redm[j * 2 + 1], redm[(128 + j) * 2 + 1]);
        float u0 = lo2(s1t) * (1.0f / 256.0f), u1 = hi2(s1t) * (1.0f / 256.0f);
        float v0 = lo2(s2t) * (1.0f / 256.0f) - u0 * u0;
        float v1 = hi2(s2t) * (1.0f / 256.0f) - u1 * u1;
        sm[SM_US + j] = u0;       sm[SM_US + j + 128] = u1;
        sm[SM_RS + j] = rsqrtf(v0 + 1e-6f);
        sm[SM_RS + j + 128] = rsqrtf(v1 + 1e-6f);
    }
    __syncthreads();

    // ---- correct scores, write S[hg][pos]
    {
        u64 nu0 = dup2(-sm[SM_US + j]);
        u64 nu1 = dup2(-sm[SM_US + j + 128]);
        u64 r0  = dup2(sm[SM_RS + j]);
        u64 r1  = dup2(sm[SM_RS + j + 128]);
        const u64* csb = reinterpret_cast<const u64*>(sm + SM_CSB);
#pragma unroll
        for (int oo = 0; oo < 8; oo++) {
            int o = og * 16 + oo * 2;
            u64 cs2 = csb[o >> 1];
            u64 b2  = csb[16 + (o >> 1)];
            u64 sc0 = ffma2(ffma2(cs2, nu0, acc0[oo]), r0, b2);
            u64 sc1 = ffma2(ffma2(cs2, nu1, acc1[oo]), r1, b2);
            sm[SM_S + o * 256 + j]             = lo2(sc0);
            sm[SM_S + (o + 1) * 256 + j]       = hi2(sc0);
            sm[SM_S + o * 256 + j + 128]       = lo2(sc1);
            sm[SM_S + (o + 1) * 256 + j + 128] = hi2(sc1);
        }
    }
    __syncthreads();

    // ---- softmax: thread = position, 4 heads x 8 keys
    {
        int p = tid;
#pragma unroll
        for (int h = 0; h < 4; h++) {
            float v[8], m = -1e30f;
#pragma unroll
            for (int g = 0; g < 8; g++) {
                v[g] = sm[SM_S + (h * 8 + g) * 256 + p];
                m = fmaxf(m, v[g]);
            }
            float ssum = 0.f;
#pragma unroll
            for (int g = 0; g < 8; g++) { v[g] = __expf(v[g] - m); ssum += v[g]; }
            float inv = 1.0f / ssum;
#pragma unroll
            for (int g = 0; g < 8; g++)
                sm[SM_S + (h * 8 + g) * 256 + p] = v[g] * inv;
        }
    }
    __syncthreads();

    // ---- GEMM2: out[o][p] = sum_k A[k][p] * P[k][o]
    float* ob = out + (size_t)b * C * NPOS + n0;
    for (int oc = 0; oc < 8; oc++) {
        u64 c0[8], c1[8];
#pragma unroll
        for (int k = 0; k < 8; k++) { c0[k] = 0ull; c1[k] = 0ull; }
        int obase = oc * 32 + og * 16;
#pragma unroll 8
        for (int k = 0; k < 32; k++) {
            float a0 = sm[SM_S + k * 256 + j];
            float a1 = sm[SM_S + k * 256 + j + 128];
            u64 a0d = dup2(a0), a1d = dup2(a1);
            const ulonglong2* wq = reinterpret_cast<const ulonglong2*>(
                sm + SM_W + k * 256 + obase);
#pragma unroll
            for (int pr = 0; pr < 4; pr++) {
                ulonglong2 wv = wq[pr];
                c0[pr * 2]     = ffma2(wv.x, a0d, c0[pr * 2]);
                c0[pr * 2 + 1] = ffma2(wv.y, a0d, c0[pr * 2 + 1]);
                c1[pr * 2]     = ffma2(wv.x, a1d, c1[pr * 2]);
                c1[pr * 2 + 1] = ffma2(wv.y, a1d, c1[pr * 2 + 1]);
            }
        }
#pragma unroll
        for (int oo = 0; oo < 8; oo++) {
            int o = obase + oo * 2;
            ob[(size_t)o * NPOS + j]             = lo2(c0[oo]);
            ob[(size_t)(o + 1) * NPOS + j]       = hi2(c0[oo]);
            ob[(size_t)o * NPOS + j + 128]       = lo2(c1[oo]);
            ob[(size_t)(o + 1) * NPOS + j + 128] = hi2(c1[oo]);
        }
    }
}

// ---------------------------------------------------------------------------
extern "C" void kernel_launch(void* const* d_in, const int* in_sizes, int n_in,
                              void* d_out, int out_size) {
    const float* x2     = (const float*)d_in[0];
    const float* x1_low = (const float*)d_in[1];
    const float* q_w    = (const float*)d_in[2];
    const float* k_w    = (const float*)d_in[3];
    const float* v_w    = (const float*)d_in[4];
    const float* dw_w   = (const float*)d_in[5];
    const float* proj_w = (const float*)d_in[6];
    const float* nq_w   = (const float*)d_in[7];
    const float* nq_b   = (const float*)d_in[8];
    const float* nkv_w  = (const float*)d_in[9];
    const float* nkv_b  = (const float*)d_in[10];
    float* out = (float*)d_out;

    cudaFuncSetAttribute(k_main, cudaFuncAttributeMaxDynamicSharedMemorySize,
                         SM_TOT * sizeof(float));

    k_tokens<<<512, 256>>>(x1_low, dw_w);
    k_kv<<<16, 256>>>(k_w, v_w, nkv_w, nkv_b);
    k_foldA<<<64, 256>>>(q_w, nq_w, nq_b);
    k_foldB<<<256, 256>>>(proj_w);
    k_main<<<256, 256, SM_TOT * sizeof(float)>>>(x2, out);
}

// round 8
// speedup vs baseline: 1.5058x; 1.1869x over previous
#include <cuda_runtime.h>
#include <math.h>

#define C 256
#define NPOS 32768
#define G 8
#define H 4

typedef unsigned long long u64;

// ---- scratch --------------------------------------------------------------
__device__ float g_tokens[2 * C * G];     // [b][c][g]
__device__ float g_K[2 * H * 64 * G];     // [b][h][d][g], pre-scaled by 1/8
__device__ float g_V[2 * H * G * 64];     // [b][h][g][d]
__device__ float g_Ms[2 * C * 32];        // [b][c][hg]  folded score matrix * nq_w
__device__ float g_P[2 * 32 * C];         // [b][hg][o]  folded output matrix
__device__ float g_cs[2 * 32];            // colsum of Ms*nq_w
__device__ float g_bias[2 * 32];          // Ms_raw . nq_b

// ---- f32x2 helpers ----------------------------------------------------------
__device__ __forceinline__ u64 dup2(float a) {
    u64 r; asm("mov.b64 %0,{%1,%1};" : "=l"(r) : "f"(a)); return r;
}
__device__ __forceinline__ u64 pack2(float a, float b) {
    u64 r; asm("mov.b64 %0,{%1,%2};" : "=l"(r) : "f"(a), "f"(b)); return r;
}
__device__ __forceinline__ u64 ffma2(u64 a, u64 b, u64 c) {
    u64 d; asm("fma.rn.f32x2 %0,%1,%2,%3;" : "=l"(d) : "l"(a), "l"(b), "l"(c)); return d;
}
__device__ __forceinline__ u64 add2(u64 a, u64 b) {
    u64 d; asm("add.rn.f32x2 %0,%1,%2;" : "=l"(d) : "l"(a), "l"(b)); return d;
}
__device__ __forceinline__ float lo2(u64 v) { return __uint_as_float((unsigned)v); }
__device__ __forceinline__ float hi2(u64 v) { return __uint_as_float((unsigned)(v >> 32)); }

__device__ __forceinline__ void cpa16(unsigned s, const void* g) {
    asm volatile("cp.async.cg.shared.global [%0], [%1], 16;" :: "r"(s), "l"(g));
}
__device__ __forceinline__ void cpa_commit() { asm volatile("cp.async.commit_group;"); }
__device__ __forceinline__ void cpa_wait1() { asm volatile("cp.async.wait_group 1;"); }
__device__ __forceinline__ void cpa_wait0() { asm volatile("cp.async.wait_group 0;"); }

// ---------------------------------------------------------------------------
// pool 16^3 -> 2^3 + depthwise 3^3 conv (SAME) + residual — vectorized loads
// ---------------------------------------------------------------------------
__global__ void k_tokens(const float* __restrict__ x1,
                         const float* __restrict__ dw_w) {
    int bc = blockIdx.x;               // b*256 + c
    int c = bc & 255;
    const float* xp = x1 + (size_t)bc * 4096;
    int tid = threadIdx.x;
    int w = tid >> 5, lane = tid & 31;
    int gz = w >> 2, gy = (w >> 1) & 1, gx = w & 1;
    float s = 0.f;
#pragma unroll
    for (int p = 0; p < 2; p++) {
        int idx = lane + p * 32;       // 0..63 -> (lz,ly)
        int lz = idx >> 3, ly = idx & 7;
        const float4* r = reinterpret_cast<const float4*>(
            xp + (gz * 8 + lz) * 256 + (gy * 8 + ly) * 16 + gx * 8);
        float4 a = r[0], b4 = r[1];
        s += a.x + a.y + a.z + a.w + b4.x + b4.y + b4.z + b4.w;
    }
#pragma unroll
    for (int off = 16; off; off >>= 1) s += __shfl_down_sync(0xffffffffu, s, off);
    __shared__ float pooled[8];
    if (lane == 0) pooled[w] = s * (1.0f / 512.0f);
    __syncthreads();
    if (tid < 8) {
        int z = tid >> 2, y = (tid >> 1) & 1, x = tid & 1;
        float acc = 0.f;
        for (int dz = -1; dz <= 1; dz++)
            for (int dy = -1; dy <= 1; dy++)
                for (int dx = -1; dx <= 1; dx++) {
                    int nz = z + dz, ny = y + dy, nx = x + dx;
                    if ((unsigned)nz < 2u && (unsigned)ny < 2u && (unsigned)nx < 2u)
                        acc += dw_w[c * 27 + (dz + 1) * 9 + (dy + 1) * 3 + (dx + 1)] *
                               pooled[nz * 4 + ny * 2 + nx];
                }
        g_tokens[bc * 8 + tid] = pooled[tid] + acc;
    }
}

// ---------------------------------------------------------------------------
// LN(tokens) over channels, K (prescaled), V.
// grid 64 = (b*8+g)*4 + quarter; LN recomputed per quarter; 8 outputs/warp
// ---------------------------------------------------------------------------
__global__ void k_kv(const float* __restrict__ k_w, const float* __restrict__ v_w,
                     const float* __restrict__ nkv_w, const float* __restrict__ nkv_b) {
    int bid = blockIdx.x;
    int q = bid & 3;
    int bg = bid >> 2;
    int b = bg >> 3, g = bg & 7;
    int tid = threadIdx.x;             // 256
    int w = tid >> 5, lane = tid & 31;
    __shared__ float tok[256], tk[256], red[16];
    __shared__ float uu, rstd;
    float t = g_tokens[(b * 256 + tid) * 8 + g];
    tok[tid] = t;
    float s1 = t, s2 = t * t;
#pragma unroll
    for (int off = 16; off; off >>= 1) {
        s1 += __shfl_down_sync(0xffffffffu, s1, off);
        s2 += __shfl_down_sync(0xffffffffu, s2, off);
    }
    if (lane == 0) { red[w] = s1; red[8 + w] = s2; }
    __syncthreads();
    if (tid == 0) {
        float a = 0.f, qq = 0.f;
        for (int i = 0; i < 8; i++) { a += red[i]; qq += red[8 + i]; }
        float u = a * (1.0f / 256.0f);
        float var = qq * (1.0f / 256.0f) - u * u;
        uu = u; rstd = rsqrtf(var + 1e-6f);
    }
    __syncthreads();
    tk[tid] = (t - uu) * rstd * nkv_w[tid] + nkv_b[tid];
    __syncthreads();

#pragma unroll
    for (int oo = 0; oo < 8; oo++) {
        int o = q * 64 + w * 8 + oo;
        const float* kr = k_w + o * 256;
        const float* vr = v_w + o * 256;
        float pk = 0.f, pv = 0.f;
#pragma unroll
        for (int i = 0; i < 8; i++) {
            int c2 = lane + 32 * i;
            pk += kr[c2] * tk[c2];
            pv += vr[c2] * tok[c2];
        }
#pragma unroll
        for (int off = 16; off; off >>= 1) {
            pk += __shfl_down_sync(0xffffffffu, pk, off);
            pv += __shfl_down_sync(0xffffffffu, pv, off);
        }
        if (lane == 0) {
            int h = o >> 6, d = o & 63;
            g_K[((b * 4 + h) * 64 + d) * 8 + g] = pk * 0.125f;
            g_V[((b * 4 + h) * 8 + g) * 64 + d] = pv;
        }
    }
}

// ---------------------------------------------------------------------------
// foldA: Ms premul by nq_w, plus cs/bias. grid 64 = (b,hg), thread = c
// ---------------------------------------------------------------------------
__global__ void k_foldA(const float* __restrict__ q_w,
                        const float* __restrict__ nq_w,
                        const float* __restrict__ nq_b) {
    int bhg = blockIdx.x;
    int b = bhg >> 5, hg = bhg & 31, h = hg >> 3, g = hg & 7;
    int t = threadIdx.x;
    __shared__ float kd[64];
    __shared__ float r1[8], r2[8];
    if (t < 64) kd[t] = g_K[((b * 4 + h) * 64 + t) * 8 + g];
    __syncthreads();
    float s = 0.f;
    const float* qp = q_w + (h * 64) * 256 + t;
#pragma unroll 8
    for (int d = 0; d < 64; d++) s += qp[d * 256] * kd[d];
    float sp = s * nq_w[t];
    float sb = s * nq_b[t];
    g_Ms[(b * 256 + t) * 32 + hg] = sp;
    float a1 = sp, a2 = sb;
#pragma unroll
    for (int off = 16; off; off >>= 1) {
        a1 += __shfl_down_sync(0xffffffffu, a1, off);
        a2 += __shfl_down_sync(0xffffffffu, a2, off);
    }
    int w = t >> 5, lane = t & 31;
    if (lane == 0) { r1[w] = a1; r2[w] = a2; }
    __syncthreads();
    if (t == 0) {
        float c1 = 0.f, c2 = 0.f;
        for (int i = 0; i < 8; i++) { c1 += r1[i]; c2 += r2[i]; }
        g_cs[b * 32 + hg] = c1;
        g_bias[b * 32 + hg] = c2;
    }
}

// ---------------------------------------------------------------------------
// foldB: P[hg][o] = sum_d proj_w[o, h*64+d] * V[h,g,d]
// grid 256 = (b,hg,quarter); warp-per-output-row, 8 rows/warp
// ---------------------------------------------------------------------------
__global__ void k_foldB(const float* __restrict__ proj_w) {
    int bid = blockIdx.x;              // (b*32+hg)*4 + q
    int q = bid & 3;
    int bhg = bid >> 2;
    int b = bhg >> 5, hg = bhg & 31, h = hg >> 3, g = hg & 7;
    int tid = threadIdx.x;
    int w = tid >> 5, lane = tid & 31;
    __shared__ float vd[64];
    if (tid < 64) vd[tid] = g_V[((b * 4 + h) * 8 + g) * 64 + tid];
    __syncthreads();
#pragma unroll
    for (int oo = 0; oo < 8; oo++) {
        int o = q * 64 + w * 8 + oo;
        const float* pw = proj_w + o * 256 + h * 64;
        float p = pw[lane] * vd[lane] + pw[32 + lane] * vd[32 + lane];
#pragma unroll
        for (int off = 16; off; off >>= 1)
            p += __shfl_down_sync(0xffffffffu, p, off);
        if (lane == 0) g_P[b * 8192 + hg * 256 + o] = p;
    }
}

// ---------------------------------------------------------------------------
// main fused kernel: 256 positions/block, 16 chunks x 16 channels,
// double-buffer cp.async (2 syncs/chunk, r4-proven), P time-muxed after GEMM1.
// smem 70 KB -> 3 blocks/SM.
// ---------------------------------------------------------------------------
#define SM_W   0              /* 8192: Ms, later P */
#define SM_X   8192           /* 2 x 4096 double buffer; S[32][256] after GEMM1 */
#define SM_S   8192
#define SM_RED 16384          /* 512 u64 = 1024 floats */
#define SM_US  17408
#define SM_RS  17664
#define SM_CSB 17920          /* cs[32] bias[32] */
#define SM_TOT 17984

__global__ void __launch_bounds__(256, 3) k_main(
    const float* __restrict__ x2, float* __restrict__ out) {
    extern __shared__ float sm[];
    int tid = threadIdx.x;
    int j = tid & 127, og = tid >> 7;
    int b = blockIdx.x >> 7;
    int n0 = (blockIdx.x & 127) * 256;

    const float* xb = x2 + (size_t)b * C * NPOS + n0;
    unsigned xs_u32 = (unsigned)__cvta_generic_to_shared(sm + SM_X);

    // prologue: chunk 0 into buf 0
    {
#pragma unroll
        for (int it = 0; it < 4; it++) {
            int idx = tid + it * 256;
            int row = idx >> 6, col = idx & 63;
            cpa16(xs_u32 + (unsigned)(row * 1024 + col * 16),
                  xb + (size_t)row * NPOS + col * 4);
        }
        cpa_commit();
    }

    // Ms + cs/bias
    for (int i = tid; i < 8192; i += 256) sm[SM_W + i] = g_Ms[b * 8192 + i];
    if (tid < 32) {
        sm[SM_CSB + tid]      = g_cs[b * 32 + tid];
        sm[SM_CSB + 32 + tid] = g_bias[b * 32 + tid];
    }

    u64 acc0[8], acc1[8], s1p = 0ull, s2p = 0ull;
#pragma unroll
    for (int k = 0; k < 8; k++) { acc0[k] = 0ull; acc1[k] = 0ull; }

    for (int ch = 0; ch < 16; ch++) {
        if (ch < 15) {
            const float* src = xb + (size_t)((ch + 1) * 16) * NPOS;
            unsigned dst = xs_u32 + ((unsigned)((ch + 1) & 1)) * 16384u;
#pragma unroll
            for (int it = 0; it < 4; it++) {
                int idx = tid + it * 256;
                int row = idx >> 6, col = idx & 63;
                cpa16(dst + (unsigned)(row * 1024 + col * 16),
                      src + (size_t)row * NPOS + col * 4);
            }
            cpa_commit();
            cpa_wait1();
        } else {
            cpa_wait0();
        }
        __syncthreads();

        const float* Xc = sm + SM_X + ((ch & 1) << 12);
        bool dostats = (og == (ch >> 3));
#pragma unroll
        for (int cl = 0; cl < 16; cl++) {
            float x0 = Xc[cl * 256 + j];
            float x1 = Xc[cl * 256 + j + 128];
            u64 x0d = dup2(x0), x1d = dup2(x1);
            const ulonglong2* wq = reinterpret_cast<const ulonglong2*>(
                sm + SM_W + (ch * 16 + cl) * 32 + og * 16);
#pragma unroll
            for (int pr = 0; pr < 4; pr++) {
                ulonglong2 wv = wq[pr];
                acc0[pr * 2]     = ffma2(wv.x, x0d, acc0[pr * 2]);
                acc0[pr * 2 + 1] = ffma2(wv.y, x0d, acc0[pr * 2 + 1]);
                acc1[pr * 2]     = ffma2(wv.x, x1d, acc1[pr * 2]);
                acc1[pr * 2 + 1] = ffma2(wv.y, x1d, acc1[pr * 2 + 1]);
            }
            if (dostats) {
                u64 xp = pack2(x0, x1);
                s1p = add2(s1p, xp);
                s2p = ffma2(xp, xp, s2p);
            }
        }
        __syncthreads();   // all warps done with this buffer before next prefetch
    }

    // ---- reduce LN stats; load P into W region (Ms dead)
    u64* redm = reinterpret_cast<u64*>(sm + SM_RED);
    redm[(og * 128 + j) * 2]     = s1p;
    redm[(og * 128 + j) * 2 + 1] = s2p;
    __syncthreads();
    for (int i = tid; i < 8192; i += 256) sm[SM_W + i] = g_P[b * 8192 + i];
    if (og == 0) {
        u64 s1t = add2(redm[j * 2], redm[(128 + j) * 2]);
        u64 s2t = add2(redm[j * 2 + 1], redm[(128 + j) * 2 + 1]);
        float u0 = lo2(s1t) * (1.0f / 256.0f), u1 = hi2(s1t) * (1.0f / 256.0f);
        float v0 = lo2(s2t) * (1.0f / 256.0f) - u0 * u0;
        float v1 = hi2(s2t) * (1.0f / 256.0f) - u1 * u1;
        sm[SM_US + j] = u0;       sm[SM_US + j + 128] = u1;
        sm[SM_RS + j] = rsqrtf(v0 + 1e-6f);
        sm[SM_RS + j + 128] = rsqrtf(v1 + 1e-6f);
    }
    __syncthreads();

    // ---- correct scores, write S[hg][pos]
    {
        u64 nu0 = dup2(-sm[SM_US + j]);
        u64 nu1 = dup2(-sm[SM_US + j + 128]);
        u64 r0  = dup2(sm[SM_RS + j]);
        u64 r1  = dup2(sm[SM_RS + j + 128]);
        const u64* csb = reinterpret_cast<const u64*>(sm + SM_CSB);
#pragma unroll
        for (int oo = 0; oo < 8; oo++) {
            int o = og * 16 + oo * 2;
            u64 cs2 = csb[o >> 1];
            u64 b2  = csb[16 + (o >> 1)];
            u64 sc0 = ffma2(ffma2(cs2, nu0, acc0[oo]), r0, b2);
            u64 sc1 = ffma2(ffma2(cs2, nu1, acc1[oo]), r1, b2);
            sm[SM_S + o * 256 + j]             = lo2(sc0);
            sm[SM_S + (o + 1) * 256 + j]       = hi2(sc0);
            sm[SM_S + o * 256 + j + 128]       = lo2(sc1);
            sm[SM_S + (o + 1) * 256 + j + 128] = hi2(sc1);
        }
    }
    __syncthreads();

    // ---- softmax: thread = position, 4 heads x 8 keys
    {
        int p = tid;
#pragma unroll
        for (int h = 0; h < 4; h++) {
            float v[8], m = -1e30f;
#pragma unroll
            for (int g = 0; g < 8; g++) {
                v[g] = sm[SM_S + (h * 8 + g) * 256 + p];
                m = fmaxf(m, v[g]);
            }
            float ssum = 0.f;
#pragma unroll
            for (int g = 0; g < 8; g++) { v[g] = __expf(v[g] - m); ssum += v[g]; }
            float inv = 1.0f / ssum;
#pragma unroll
            for (int g = 0; g < 8; g++)
                sm[SM_S + (h * 8 + g) * 256 + p] = v[g] * inv;
        }
    }
    __syncthreads();

    // ---- GEMM2: out[o][p] = sum_k A[k][p] * P[k][o]
    float* ob = out + (size_t)b * C * NPOS + n0;
    for (int oc = 0; oc < 8; oc++) {
        u64 c0[8], c1[8];
#pragma unroll
        for (int k = 0; k < 8; k++) { c0[k] = 0ull; c1[k] = 0ull; }
        int obase = oc * 32 + og * 16;
#pragma unroll 8
        for (int k = 0; k < 32; k++) {
            float a0 = sm[SM_S + k * 256 + j];
            float a1 = sm[SM_S + k * 256 + j + 128];
            u64 a0d = dup2(a0), a1d = dup2(a1);
            const ulonglong2* wq = reinterpret_cast<const ulonglong2*>(
                sm + SM_W + k * 256 + obase);
#pragma unroll
            for (int pr = 0; pr < 4; pr++) {
                ulonglong2 wv = wq[pr];
                c0[pr * 2]     = ffma2(wv.x, a0d, c0[pr * 2]);
                c0[pr * 2 + 1] = ffma2(wv.y, a0d, c0[pr * 2 + 1]);
                c1[pr * 2]     = ffma2(wv.x, a1d, c1[pr * 2]);
                c1[pr * 2 + 1] = ffma2(wv.y, a1d, c1[pr * 2 + 1]);
            }
        }
#pragma unroll
        for (int oo = 0; oo < 8; oo++) {
            int o = obase + oo * 2;
            ob[(size_t)o * NPOS + j]             = lo2(c0[oo]);
            ob[(size_t)(o + 1) * NPOS + j]       = hi2(c0[oo]);
            ob[(size_t)o * NPOS + j + 128]       = lo2(c1[oo]);
            ob[(size_t)(o + 1) * NPOS + j + 128] = hi2(c1[oo]);
        }
    }
}

// ---------------------------------------------------------------------------
extern "C" void kernel_launch(void* const* d_in, const int* in_sizes, int n_in,
                              void* d_out, int out_size) {
    const float* x2     = (const float*)d_in[0];
    const float* x1_low = (const float*)d_in[1];
    const float* q_w    = (const float*)d_in[2];
    const float* k_w    = (const float*)d_in[3];
    const float* v_w    = (const float*)d_in[4];
    const float* dw_w   = (const float*)d_in[5];
    const float* proj_w = (const float*)d_in[6];
    const float* nq_w   = (const float*)d_in[7];
    const float* nq_b   = (const float*)d_in[8];
    const float* nkv_w  = (const float*)d_in[9];
    const float* nkv_b  = (const float*)d_in[10];
    float* out = (float*)d_out;

    cudaFuncSetAttribute(k_main, cudaFuncAttributeMaxDynamicSharedMemorySize,
                         SM_TOT * sizeof(float));

    k_tokens<<<512, 256>>>(x1_low, dw_w);
    k_kv<<<64, 256>>>(k_w, v_w, nkv_w, nkv_b);
    k_foldA<<<64, 256>>>(q_w, nq_w, nq_b);
    k_foldB<<<256, 256>>>(proj_w);
    k_main<<<256, 256, SM_TOT * sizeof(float)>>>(x2, out);
}

// round 10
// speedup vs baseline: 1.9207x; 1.2755x over previous
#include <cuda_runtime.h>
#include <cuda_bf16.h>
#include <cstdint>
#include <math.h>

#define C 256
#define NPOS 32768
#define G 8
#define H 4

// ---- scratch --------------------------------------------------------------
__device__ float g_tokens[2 * C * G];          // [b][c][g]
__device__ float g_K[2 * H * 64 * G];          // [b][h][d][g], pre-scaled by 1/8
__device__ float g_V[2 * H * G * 64];          // [b][h][g][d]
__device__ __nv_bfloat16 g_B1h[2 * 32 * 256];  // [b][hg][c]  Ms~^T hi
__device__ __nv_bfloat16 g_B1l[2 * 32 * 256];  // [b][hg][c]  Ms~^T lo
__device__ __nv_bfloat16 g_B2h[2 * 256 * 32];  // [b][o][hg]  P^T hi
__device__ __nv_bfloat16 g_B2l[2 * 256 * 32];  // [b][o][hg]  P^T lo
__device__ float g_cs[2 * 32];                 // colsum of Ms~
__device__ float g_bias[2 * 32];               // Ms_raw . nq_b

// ---- helpers ----------------------------------------------------------------
__device__ __forceinline__ uint32_t smem_to_u32(const void* p) {
    uint32_t a;
    asm("{ .reg .u64 t; cvta.to.shared.u64 t, %1; cvt.u32.u64 %0, t; }"
        : "=r"(a) : "l"(p));
    return a;
}
__device__ __forceinline__ void cpa16(unsigned s, const void* g) {
    asm volatile("cp.async.cg.shared.global [%0], [%1], 16;" :: "r"(s), "l"(g));
}
__device__ __forceinline__ void cpa_commit() { asm volatile("cp.async.commit_group;"); }
__device__ __forceinline__ void cpa_wait1() { asm volatile("cp.async.wait_group 1;"); }
__device__ __forceinline__ void cpa_wait0() { asm volatile("cp.async.wait_group 0;"); }

// pack two floats into bf16x2: low half = first arg
__device__ __forceinline__ uint32_t bf16pack(float lo, float hi) {
    uint32_t r;
    asm("cvt.rn.bf16x2.f32 %0, %1, %2;" : "=r"(r) : "f"(hi), "f"(lo));
    return r;
}

// D += A(16x16 bf16 row) * B(16x8 bf16 col), fp32 accum
__device__ __forceinline__ void mma16816(float* d, const uint32_t* a, const uint32_t* b) {
    asm volatile(
        "mma.sync.aligned.m16n8k16.row.col.f32.bf16.bf16.f32 "
        "{%0,%1,%2,%3}, {%4,%5,%6,%7}, {%8,%9}, {%0,%1,%2,%3};"
        : "+f"(d[0]), "+f"(d[1]), "+f"(d[2]), "+f"(d[3])
        : "r"(a[0]), "r"(a[1]), "r"(a[2]), "r"(a[3]), "r"(b[0]), "r"(b[1]));
}

// ---------------------------------------------------------------------------
// pool 16^3 -> 2^3 + depthwise 3^3 conv (SAME) + residual
// ---------------------------------------------------------------------------
__global__ void k_tokens(const float* __restrict__ x1,
                         const float* __restrict__ dw_w) {
    int bc = blockIdx.x;
    int c = bc & 255;
    const float* xp = x1 + (size_t)bc * 4096;
    int tid = threadIdx.x;
    int w = tid >> 5, lane = tid & 31;
    int gz = w >> 2, gy = (w >> 1) & 1, gx = w & 1;
    float s = 0.f;
#pragma unroll
    for (int p = 0; p < 2; p++) {
        int idx = lane + p * 32;
        int lz = idx >> 3, ly = idx & 7;
        const float4* r = reinterpret_cast<const float4*>(
            xp + (gz * 8 + lz) * 256 + (gy * 8 + ly) * 16 + gx * 8);
        float4 a = r[0], b4 = r[1];
        s += a.x + a.y + a.z + a.w + b4.x + b4.y + b4.z + b4.w;
    }
#pragma unroll
    for (int off = 16; off; off >>= 1) s += __shfl_down_sync(0xffffffffu, s, off);
    __shared__ float pooled[8];
    if (lane == 0) pooled[w] = s * (1.0f / 512.0f);
    __syncthreads();
    if (tid < 8) {
        int z = tid >> 2, y = (tid >> 1) & 1, x = tid & 1;
        float acc = 0.f;
        for (int dz = -1; dz <= 1; dz++)
            for (int dy = -1; dy <= 1; dy++)
                for (int dx = -1; dx <= 1; dx++) {
                    int nz = z + dz, ny = y + dy, nx = x + dx;
                    if ((unsigned)nz < 2u && (unsigned)ny < 2u && (unsigned)nx < 2u)
                        acc += dw_w[c * 27 + (dz + 1) * 9 + (dy + 1) * 3 + (dx + 1)] *
                               pooled[nz * 4 + ny * 2 + nx];
                }
        g_tokens[bc * 8 + tid] = pooled[tid] + acc;
    }
}

// ---------------------------------------------------------------------------
// LN(tokens), K (prescaled), V.  grid 64 = (b*8+g)*4 + quarter
// ---------------------------------------------------------------------------
__global__ void k_kv(const float* __restrict__ k_w, const float* __restrict__ v_w,
                     const float* __restrict__ nkv_w, const float* __restrict__ nkv_b) {
    int bid = blockIdx.x;
    int q = bid & 3;
    int bg = bid >> 2;
    int b = bg >> 3, g = bg & 7;
    int tid = threadIdx.x;
    int w = tid >> 5, lane = tid & 31;
    __shared__ float tok[256], tk[256], red[16];
    __shared__ float uu, rstd;
    float t = g_tokens[(b * 256 + tid) * 8 + g];
    tok[tid] = t;
    float s1 = t, s2 = t * t;
#pragma unroll
    for (int off = 16; off; off >>= 1) {
        s1 += __shfl_down_sync(0xffffffffu, s1, off);
        s2 += __shfl_down_sync(0xffffffffu, s2, off);
    }
    if (lane == 0) { red[w] = s1; red[8 + w] = s2; }
    __syncthreads();
    if (tid == 0) {
        float a = 0.f, qq = 0.f;
        for (int i = 0; i < 8; i++) { a += red[i]; qq += red[8 + i]; }
        float u = a * (1.0f / 256.0f);
        float var = qq * (1.0f / 256.0f) - u * u;
        uu = u; rstd = rsqrtf(var + 1e-6f);
    }
    __syncthreads();
    tk[tid] = (t - uu) * rstd * nkv_w[tid] + nkv_b[tid];
    __syncthreads();
#pragma unroll
    for (int oo = 0; oo < 8; oo++) {
        int o = q * 64 + w * 8 + oo;
        const float* kr = k_w + o * 256;
        const float* vr = v_w + o * 256;
        float pk = 0.f, pv = 0.f;
#pragma unroll
        for (int i = 0; i < 8; i++) {
            int c2 = lane + 32 * i;
            pk += kr[c2] * tk[c2];
            pv += vr[c2] * tok[c2];
        }
#pragma unroll
        for (int off = 16; off; off >>= 1) {
            pk += __shfl_down_sync(0xffffffffu, pk, off);
            pv += __shfl_down_sync(0xffffffffu, pv, off);
        }
        if (lane == 0) {
            int h = o >> 6, d = o & 63;
            g_K[((b * 4 + h) * 64 + d) * 8 + g] = pk * 0.125f;
            g_V[((b * 4 + h) * 8 + g) * 64 + d] = pv;
        }
    }
}

// ---------------------------------------------------------------------------
// foldA: B1 = (Ms * nq_w)^T as bf16 hi/lo + cs/bias. grid 64 = (b,hg)
// ---------------------------------------------------------------------------
__global__ void k_foldA(const float* __restrict__ q_w,
                        const float* __restrict__ nq_w,
                        const float* __restrict__ nq_b) {
    int bhg = blockIdx.x;
    int b = bhg >> 5, hg = bhg & 31, h = hg >> 3, g = hg & 7;
    int t = threadIdx.x;
    __shared__ float kd[64];
    __shared__ float r1[8], r2[8];
    if (t < 64) kd[t] = g_K[((b * 4 + h) * 64 + t) * 8 + g];
    __syncthreads();
    float s = 0.f;
    const float* qp = q_w + (h * 64) * 256 + t;
#pragma unroll 8
    for (int d = 0; d < 64; d++) s += qp[d * 256] * kd[d];
    float sp = s * nq_w[t];
    float sb = s * nq_b[t];
    __nv_bfloat16 hb = __float2bfloat16(sp);
    g_B1h[b * 8192 + hg * 256 + t] = hb;
    g_B1l[b * 8192 + hg * 256 + t] = __float2bfloat16(sp - __bfloat162float(hb));
    float a1 = sp, a2 = sb;
#pragma unroll
    for (int off = 16; off; off >>= 1) {
        a1 += __shfl_down_sync(0xffffffffu, a1, off);
        a2 += __shfl_down_sync(0xffffffffu, a2, off);
    }
    int w = t >> 5, lane = t & 31;
    if (lane == 0) { r1[w] = a1; r2[w] = a2; }
    __syncthreads();
    if (t == 0) {
        float c1 = 0.f, c2 = 0.f;
        for (int i = 0; i < 8; i++) { c1 += r1[i]; c2 += r2[i]; }
        g_cs[b * 32 + hg] = c1;
        g_bias[b * 32 + hg] = c2;
    }
}

// ---------------------------------------------------------------------------
// foldB: B2 = P^T [o][hg] bf16 hi/lo. grid 256 = (b,hg,quarter)
// ---------------------------------------------------------------------------
__global__ void k_foldB(const float* __restrict__ proj_w) {
    int bid = blockIdx.x;
    int q = bid & 3;
    int bhg = bid >> 2;
    int b = bhg >> 5, hg = bhg & 31, h = hg >> 3, g = hg & 7;
    int tid = threadIdx.x;
    int w = tid >> 5, lane = tid & 31;
    __shared__ float vd[64];
    if (tid < 64) vd[tid] = g_V[((b * 4 + h) * 8 + g) * 64 + tid];
    __syncthreads();
#pragma unroll
    for (int oo = 0; oo < 8; oo++) {
        int o = q * 64 + w * 8 + oo;
        const float* pw = proj_w + o * 256 + h * 64;
        float p = pw[lane] * vd[lane] + pw[32 + lane] * vd[32 + lane];
#pragma unroll
        for (int off = 16; off; off >>= 1)
            p += __shfl_down_sync(0xffffffffu, p, off);
        if (lane == 0) {
            __nv_bfloat16 hb = __float2bfloat16(p);
            g_B2h[b * 8192 + o * 32 + hg] = hb;
            g_B2l[b * 8192 + o * 32 + hg] = __float2bfloat16(p - __bfloat162float(hb));
        }
    }
}

// ---------------------------------------------------------------------------
// main kernel (mma.sync bf16 split): 128 positions/block, 256 threads, 2/SM.
// GEMM1: D1[128,32] = Xln[128,256] * Ms~ via split (xh*wh + xl*wh + xh*wl)
// GEMM2: out[128,256] = attn[128,32] * P  via same 3-term split
// smem byte offsets:
//   B1H 0 (32x132 u32-rows, 528B) | B1L 16896  -> reused as A2H/A2L
//   B2H 33792 (256x20 u32-rows, 80B) | B2L 54272
//   XS 74752 (2 x 16x132 f32) -> reused as S[128][33] f32
//   ST1 91648 | ST2 92672 | CS 93696 | BIAS 93824 | total 93952
// ---------------------------------------------------------------------------
#define SB_B1H 0
#define SB_B1L 16896
#define SB_A2H 0
#define SB_A2L 16896
#define SB_B2H 33792
#define SB_B2L 54272
#define SB_XS  74752
#define SB_S   74752
#define SB_ST1 91648
#define SB_ST2 92672
#define SB_CS  93696
#define SB_BIAS 93824
#define SB_TOT 93952

__global__ void __launch_bounds__(256, 2) k_main(
    const float* __restrict__ x2, float* __restrict__ out) {
    extern __shared__ char smc[];
    uint32_t smb = smem_to_u32(smc);
    int tid = threadIdx.x;
    int lane = tid & 31, w = tid >> 5;
    int g = lane >> 2, tg = lane & 3;
    int b = blockIdx.x >> 8;
    int n0 = (blockIdx.x & 255) * 128;
    const float* xb = x2 + (size_t)b * (C * NPOS) + n0;

    // ---- prologue: B operands (group 0), chunk 0 (group 1), cs/bias
    {
        const char* s1 = (const char*)g_B1h + b * 16384;
        const char* s2 = (const char*)g_B1l + b * 16384;
        for (int i = tid; i < 1024; i += 256) {
            int r = i >> 5, c2 = i & 31;
            cpa16(smb + SB_B1H + r * 528 + c2 * 16, s1 + r * 512 + c2 * 16);
            cpa16(smb + SB_B1L + r * 528 + c2 * 16, s2 + r * 512 + c2 * 16);
        }
        const char* s3 = (const char*)g_B2h + b * 16384;
        const char* s4 = (const char*)g_B2l + b * 16384;
        for (int i = tid; i < 1024; i += 256) {
            int r = i >> 2, c2 = i & 3;
            cpa16(smb + SB_B2H + r * 80 + c2 * 16, s3 + r * 64 + c2 * 16);
            cpa16(smb + SB_B2L + r * 80 + c2 * 16, s4 + r * 64 + c2 * 16);
        }
        cpa_commit();
        for (int i = tid; i < 512; i += 256) {
            int r = i >> 5, c2 = i & 31;
            cpa16(smb + SB_XS + r * 528 + c2 * 16, xb + (size_t)r * NPOS + c2 * 4);
        }
        cpa_commit();
        if (tid < 32) ((float*)(smc + SB_CS))[tid] = g_cs[b * 32 + tid];
        else if (tid < 64) ((float*)(smc + SB_BIAS))[tid - 32] = g_bias[b * 32 + tid - 32];
    }

    const uint32_t* b1h = (const uint32_t*)(smc + SB_B1H);
    const uint32_t* b1l = (const uint32_t*)(smc + SB_B1L);
    float d1[4][4] = {};
    float s1a = 0.f, s2a = 0.f;
    int prow = tid & 127, phalf = tid >> 7;
    int m0 = w * 16 + g, k0 = 2 * tg;

    for (int ch = 0; ch < 16; ch++) {
        if (ch < 15) {
            const float* src = xb + (size_t)((ch + 1) * 16) * NPOS;
            unsigned dst = smb + SB_XS + ((unsigned)((ch + 1) & 1)) * 8448u;
            for (int i = tid; i < 512; i += 256) {
                int r = i >> 5, c2 = i & 31;
                cpa16(dst + r * 528 + c2 * 16, src + (size_t)r * NPOS + c2 * 4);
            }
            cpa_commit();
            cpa_wait1();
        } else {
            cpa_wait0();
        }
        __syncthreads();
        const float* Xb = (const float*)(smc + SB_XS + ((ch & 1) ? 8448 : 0));

        // LN stats: thread covers 8 channels of this chunk for its position
#pragma unroll
        for (int i = 0; i < 8; i++) {
            float v = Xb[(phalf * 8 + i) * 132 + prow];
            s1a += v; s2a += v * v;
        }

        // A fragment gather + hi/lo split
        float f[8];
        f[0] = Xb[k0 * 132 + m0];           f[1] = Xb[(k0 + 1) * 132 + m0];
        f[2] = Xb[k0 * 132 + m0 + 8];       f[3] = Xb[(k0 + 1) * 132 + m0 + 8];
        f[4] = Xb[(k0 + 8) * 132 + m0];     f[5] = Xb[(k0 + 9) * 132 + m0];
        f[6] = Xb[(k0 + 8) * 132 + m0 + 8]; f[7] = Xb[(k0 + 9) * 132 + m0 + 8];
        uint32_t ah[4], al[4];
#pragma unroll
        for (int qd = 0; qd < 4; qd++) {
            uint32_t hp = bf16pack(f[2 * qd], f[2 * qd + 1]);
            float r0 = f[2 * qd]     - __uint_as_float(hp << 16);
            float r1 = f[2 * qd + 1] - __uint_as_float(hp & 0xffff0000u);
            ah[qd] = hp;
            al[qd] = bf16pack(r0, r1);
        }
#pragma unroll
        for (int nb = 0; nb < 4; nb++) {
            int n = nb * 8 + g;
            uint32_t bh[2] = { b1h[n * 132 + ch * 8 + tg], b1h[n * 132 + ch * 8 + tg + 4] };
            uint32_t bl[2] = { b1l[n * 132 + ch * 8 + tg], b1l[n * 132 + ch * 8 + tg + 4] };
            mma16816(d1[nb], ah, bh);
            mma16816(d1[nb], al, bh);
            mma16816(d1[nb], ah, bl);
        }
        __syncthreads();
    }

    // ---- stats + D1 -> smem (S overlays Xs; all reads done at loop-final sync)
    ((float*)(smc + SB_ST1))[tid] = s1a;
    ((float*)(smc + SB_ST2))[tid] = s2a;
    float* S = (float*)(smc + SB_S);
#pragma unroll
    for (int nb = 0; nb < 4; nb++) {
        int n = nb * 8 + 2 * tg;
        S[m0 * 33 + n]           = d1[nb][0];
        S[m0 * 33 + n + 1]       = d1[nb][1];
        S[(m0 + 8) * 33 + n]     = d1[nb][2];
        S[(m0 + 8) * 33 + n + 1] = d1[nb][3];
    }
    __syncthreads();

    // ---- LN correction + softmax + A2 hi/lo (A2 overlays B1: GEMM1 done)
    uint32_t* a2h = (uint32_t*)(smc + SB_A2H);
    uint32_t* a2l = (uint32_t*)(smc + SB_A2L);
    if (tid < 128) {
        float t1 = ((float*)(smc + SB_ST1))[tid] + ((float*)(smc + SB_ST1))[tid + 128];
        float t2 = ((float*)(smc + SB_ST2))[tid] + ((float*)(smc + SB_ST2))[tid + 128];
        float u = t1 * (1.0f / 256.0f);
        float rstd = rsqrtf(t2 * (1.0f / 256.0f) - u * u + 1e-6f);
        const float* cs = (const float*)(smc + SB_CS);
        const float* bi = (const float*)(smc + SB_BIAS);
        float a[32];
#pragma unroll
        for (int i = 0; i < 32; i++)
            a[i] = (S[tid * 33 + i] - u * cs[i]) * rstd + bi[i];
#pragma unroll
        for (int h = 0; h < 4; h++) {
            float m = -1e30f;
#pragma unroll
            for (int g2 = 0; g2 < 8; g2++) m = fmaxf(m, a[h * 8 + g2]);
            float ssum = 0.f;
#pragma unroll
            for (int g2 = 0; g2 < 8; g2++) { a[h * 8 + g2] = __expf(a[h * 8 + g2] - m); ssum += a[h * 8 + g2]; }
            float inv = 1.0f / ssum;
#pragma unroll
            for (int g2 = 0; g2 < 8; g2++) a[h * 8 + g2] *= inv;
        }
#pragma unroll
        for (int i = 0; i < 16; i++) {
            uint32_t hp = bf16pack(a[2 * i], a[2 * i + 1]);
            float r0 = a[2 * i]     - __uint_as_float(hp << 16);
            float r1 = a[2 * i + 1] - __uint_as_float(hp & 0xffff0000u);
            a2h[tid * 20 + i] = hp;
            a2l[tid * 20 + i] = bf16pack(r0, r1);
        }
    }
    __syncthreads();

    // ---- GEMM2: out[o][p] = sum_hg attn * P
    const uint32_t* b2h = (const uint32_t*)(smc + SB_B2H);
    const uint32_t* b2l = (const uint32_t*)(smc + SB_B2L);
    uint32_t A2H[2][4], A2L[2][4];
#pragma unroll
    for (int kc = 0; kc < 2; kc++) {
        A2H[kc][0] = a2h[m0 * 20 + kc * 8 + tg];
        A2H[kc][1] = a2h[(m0 + 8) * 20 + kc * 8 + tg];
        A2H[kc][2] = a2h[m0 * 20 + kc * 8 + tg + 4];
        A2H[kc][3] = a2h[(m0 + 8) * 20 + kc * 8 + tg + 4];
        A2L[kc][0] = a2l[m0 * 20 + kc * 8 + tg];
        A2L[kc][1] = a2l[(m0 + 8) * 20 + kc * 8 + tg];
        A2L[kc][2] = a2l[m0 * 20 + kc * 8 + tg + 4];
        A2L[kc][3] = a2l[(m0 + 8) * 20 + kc * 8 + tg + 4];
    }
    float* ob = out + (size_t)b * (C * NPOS) + n0;
    for (int go = 0; go < 4; go++) {
        float d2[8][4] = {};
#pragma unroll
        for (int nb = 0; nb < 8; nb++) {
            int n = go * 64 + nb * 8 + g;
#pragma unroll
            for (int kc = 0; kc < 2; kc++) {
                uint32_t bh[2] = { b2h[n * 20 + kc * 8 + tg], b2h[n * 20 + kc * 8 + tg + 4] };
                uint32_t bl[2] = { b2l[n * 20 + kc * 8 + tg], b2l[n * 20 + kc * 8 + tg + 4] };
                mma16816(d2[nb], A2H[kc], bh);
                mma16816(d2[nb], A2L[kc], bh);
                mma16816(d2[nb], A2H[kc], bl);
            }
        }
#pragma unroll
        for (int nb = 0; nb < 8; nb++) {
            int o = go * 64 + nb * 8 + 2 * tg;
            ob[(size_t)o * NPOS + m0]           = d2[nb][0];
            ob[(size_t)(o + 1) * NPOS + m0]     = d2[nb][1];
            ob[(size_t)o * NPOS + m0 + 8]       = d2[nb][2];
            ob[(size_t)(o + 1) * NPOS + m0 + 8] = d2[nb][3];
        }
    }
}

// ---------------------------------------------------------------------------
extern "C" void kernel_launch(void* const* d_in, const int* in_sizes, int n_in,
                              void* d_out, int out_size) {
    const float* x2     = (const float*)d_in[0];
    const float* x1_low = (const float*)d_in[1];
    const float* q_w    = (const float*)d_in[2];
    const float* k_w    = (const float*)d_in[3];
    const float* v_w    = (const float*)d_in[4];
    const float* dw_w   = (const float*)d_in[5];
    const float* proj_w = (const float*)d_in[6];
    const float* nq_w   = (const float*)d_in[7];
    const float* nq_b   = (const float*)d_in[8];
    const float* nkv_w  = (const float*)d_in[9];
    const float* nkv_b  = (const float*)d_in[10];
    float* out = (float*)d_out;

    cudaFuncSetAttribute(k_main, cudaFuncAttributeMaxDynamicSharedMemorySize, SB_TOT);

    k_tokens<<<512, 256>>>(x1_low, dw_w);
    k_kv<<<64, 256>>>(k_w, v_w, nkv_w, nkv_b);
    k_foldA<<<64, 256>>>(q_w, nq_w, nq_b);
    k_foldB<<<256, 256>>>(proj_w);
    k_main<<<512, 256, SB_TOT>>>(x2, out);
}

// round 11
// speedup vs baseline: 2.1301x; 1.1090x over previous
#include <cuda_runtime.h>
#include <cuda_bf16.h>
#include <cstdint>
#include <math.h>

#define C 256
#define NPOS 32768
#define G 8
#define H 4

// ---- scratch --------------------------------------------------------------
__device__ float g_tokens[2 * C * G];          // [b][c][g]
__device__ float g_K[2 * H * 64 * G];          // [b][h][d][g], pre-scaled by 1/8
__device__ float g_V[2 * H * G * 64];          // [b][h][g][d]
__device__ __nv_bfloat16 g_B1h[2 * 32 * 256];  // [b][hg][c]  Ms~^T hi
__device__ __nv_bfloat16 g_B1l[2 * 32 * 256];  // [b][hg][c]  Ms~^T lo
__device__ __nv_bfloat16 g_B2h[2 * 256 * 32];  // [b][o][hg]  P^T hi
__device__ __nv_bfloat16 g_B2l[2 * 256 * 32];  // [b][o][hg]  P^T lo
__device__ float g_cs[2 * 32];                 // colsum of Ms~
__device__ float g_bias[2 * 32];               // Ms_raw . nq_b

// ---- helpers ----------------------------------------------------------------
__device__ __forceinline__ uint32_t smem_to_u32(const void* p) {
    uint32_t a;
    asm("{ .reg .u64 t; cvta.to.shared.u64 t, %1; cvt.u32.u64 %0, t; }"
        : "=r"(a) : "l"(p));
    return a;
}
__device__ __forceinline__ void cpa16(unsigned s, const void* g) {
    asm volatile("cp.async.cg.shared.global [%0], [%1], 16;" :: "r"(s), "l"(g));
}
__device__ __forceinline__ void cpa_commit() { asm volatile("cp.async.commit_group;"); }
__device__ __forceinline__ void cpa_wait1() { asm volatile("cp.async.wait_group 1;"); }
__device__ __forceinline__ void cpa_wait0() { asm volatile("cp.async.wait_group 0;"); }

// pack two floats into bf16x2: low half = first arg
__device__ __forceinline__ uint32_t bf16pack(float lo, float hi) {
    uint32_t r;
    asm("cvt.rn.bf16x2.f32 %0, %1, %2;" : "=r"(r) : "f"(hi), "f"(lo));
    return r;
}

// D += A(16x16 bf16 row) * B(16x8 bf16 col), fp32 accum
__device__ __forceinline__ void mma16816(float* d, const uint32_t* a, const uint32_t* b) {
    asm volatile(
        "mma.sync.aligned.m16n8k16.row.col.f32.bf16.bf16.f32 "
        "{%0,%1,%2,%3}, {%4,%5,%6,%7}, {%8,%9}, {%0,%1,%2,%3};"
        : "+f"(d[0]), "+f"(d[1]), "+f"(d[2]), "+f"(d[3])
        : "r"(a[0]), "r"(a[1]), "r"(a[2]), "r"(a[3]), "r"(b[0]), "r"(b[1]));
}

// ---------------------------------------------------------------------------
// pool 16^3 -> 2^3 + depthwise 3^3 conv (SAME) + residual
// ---------------------------------------------------------------------------
__global__ void k_tokens(const float* __restrict__ x1,
                         const float* __restrict__ dw_w) {
    int bc = blockIdx.x;
    int c = bc & 255;
    const float* xp = x1 + (size_t)bc * 4096;
    int tid = threadIdx.x;
    int w = tid >> 5, lane = tid & 31;
    int gz = w >> 2, gy = (w >> 1) & 1, gx = w & 1;
    float s = 0.f;
#pragma unroll
    for (int p = 0; p < 2; p++) {
        int idx = lane + p * 32;
        int lz = idx >> 3, ly = idx & 7;
        const float4* r = reinterpret_cast<const float4*>(
            xp + (gz * 8 + lz) * 256 + (gy * 8 + ly) * 16 + gx * 8);
        float4 a = r[0], b4 = r[1];
        s += a.x + a.y + a.z + a.w + b4.x + b4.y + b4.z + b4.w;
    }
#pragma unroll
    for (int off = 16; off; off >>= 1) s += __shfl_down_sync(0xffffffffu, s, off);
    __shared__ float pooled[8];
    if (lane == 0) pooled[w] = s * (1.0f / 512.0f);
    __syncthreads();
    if (tid < 8) {
        int z = tid >> 2, y = (tid >> 1) & 1, x = tid & 1;
        float acc = 0.f;
        for (int dz = -1; dz <= 1; dz++)
            for (int dy = -1; dy <= 1; dy++)
                for (int dx = -1; dx <= 1; dx++) {
                    int nz = z + dz, ny = y + dy, nx = x + dx;
                    if ((unsigned)nz < 2u && (unsigned)ny < 2u && (unsigned)nx < 2u)
                        acc += dw_w[c * 27 + (dz + 1) * 9 + (dy + 1) * 3 + (dx + 1)] *
                               pooled[nz * 4 + ny * 2 + nx];
                }
        g_tokens[bc * 8 + tid] = pooled[tid] + acc;
    }
}

// ---------------------------------------------------------------------------
// LN(tokens), K (prescaled), V.  grid 64 = (b*8+g)*4 + quarter
// ---------------------------------------------------------------------------
__global__ void k_kv(const float* __restrict__ k_w, const float* __restrict__ v_w,
                     const float* __restrict__ nkv_w, const float* __restrict__ nkv_b) {
    int bid = blockIdx.x;
    int q = bid & 3;
    int bg = bid >> 2;
    int b = bg >> 3, g = bg & 7;
    int tid = threadIdx.x;
    int w = tid >> 5, lane = tid & 31;
    __shared__ float tok[256], tk[256], red[16];
    __shared__ float uu, rstd;
    float t = g_tokens[(b * 256 + tid) * 8 + g];
    tok[tid] = t;
    float s1 = t, s2 = t * t;
#pragma unroll
    for (int off = 16; off; off >>= 1) {
        s1 += __shfl_down_sync(0xffffffffu, s1, off);
        s2 += __shfl_down_sync(0xffffffffu, s2, off);
    }
    if (lane == 0) { red[w] = s1; red[8 + w] = s2; }
    __syncthreads();
    if (tid == 0) {
        float a = 0.f, qq = 0.f;
        for (int i = 0; i < 8; i++) { a += red[i]; qq += red[8 + i]; }
        float u = a * (1.0f / 256.0f);
        float var = qq * (1.0f / 256.0f) - u * u;
        uu = u; rstd = rsqrtf(var + 1e-6f);
    }
    __syncthreads();
    tk[tid] = (t - uu) * rstd * nkv_w[tid] + nkv_b[tid];
    __syncthreads();
#pragma unroll
    for (int oo = 0; oo < 8; oo++) {
        int o = q * 64 + w * 8 + oo;
        const float* kr = k_w + o * 256;
        const float* vr = v_w + o * 256;
        float pk = 0.f, pv = 0.f;
#pragma unroll
        for (int i = 0; i < 8; i++) {
            int c2 = lane + 32 * i;
            pk += kr[c2] * tk[c2];
            pv += vr[c2] * tok[c2];
        }
#pragma unroll
        for (int off = 16; off; off >>= 1) {
            pk += __shfl_down_sync(0xffffffffu, pk, off);
            pv += __shfl_down_sync(0xffffffffu, pv, off);
        }
        if (lane == 0) {
            int h = o >> 6, d = o & 63;
            g_K[((b * 4 + h) * 64 + d) * 8 + g] = pk * 0.125f;
            g_V[((b * 4 + h) * 8 + g) * 64 + d] = pv;
        }
    }
}

// ---------------------------------------------------------------------------
// fused folds. blocks 0..63: B1 = (Ms*nq_w)^T hi/lo + cs/bias (thread = c)
//              blocks 64..319: B2 = P^T hi/lo (warp-per-row quarters)
// ---------------------------------------------------------------------------
__global__ void k_fold(const float* __restrict__ q_w, const float* __restrict__ proj_w,
                       const float* __restrict__ nq_w, const float* __restrict__ nq_b) {
    if (blockIdx.x < 64) {
        int bhg = blockIdx.x;
        int b = bhg >> 5, hg = bhg & 31, h = hg >> 3, g = hg & 7;
        int t = threadIdx.x;
        __shared__ float kd[64];
        __shared__ float r1[8], r2[8];
        if (t < 64) kd[t] = g_K[((b * 4 + h) * 64 + t) * 8 + g];
        __syncthreads();
        float s = 0.f;
        const float* qp = q_w + (h * 64) * 256 + t;
#pragma unroll 8
        for (int d = 0; d < 64; d++) s += qp[d * 256] * kd[d];
        float sp = s * nq_w[t];
        float sb = s * nq_b[t];
        __nv_bfloat16 hb = __float2bfloat16(sp);
        g_B1h[b * 8192 + hg * 256 + t] = hb;
        g_B1l[b * 8192 + hg * 256 + t] = __float2bfloat16(sp - __bfloat162float(hb));
        float a1 = sp, a2 = sb;
#pragma unroll
        for (int off = 16; off; off >>= 1) {
            a1 += __shfl_down_sync(0xffffffffu, a1, off);
            a2 += __shfl_down_sync(0xffffffffu, a2, off);
        }
        int w = t >> 5, lane = t & 31;
        if (lane == 0) { r1[w] = a1; r2[w] = a2; }
        __syncthreads();
        if (t == 0) {
            float c1 = 0.f, c2 = 0.f;
            for (int i = 0; i < 8; i++) { c1 += r1[i]; c2 += r2[i]; }
            g_cs[b * 32 + hg] = c1;
            g_bias[b * 32 + hg] = c2;
        }
    } else {
        int bid = blockIdx.x - 64;
        int q = bid & 3;
        int bhg = bid >> 2;
        int b = bhg >> 5, hg = bhg & 31, h = hg >> 3, g = hg & 7;
        int tid = threadIdx.x;
        int w = tid >> 5, lane = tid & 31;
        __shared__ float vd[64];
        if (tid < 64) vd[tid] = g_V[((b * 4 + h) * 8 + g) * 64 + tid];
        __syncthreads();
#pragma unroll
        for (int oo = 0; oo < 8; oo++) {
            int o = q * 64 + w * 8 + oo;
            const float* pw = proj_w + o * 256 + h * 64;
            float p = pw[lane] * vd[lane] + pw[32 + lane] * vd[32 + lane];
#pragma unroll
            for (int off = 16; off; off >>= 1)
                p += __shfl_down_sync(0xffffffffu, p, off);
            if (lane == 0) {
                __nv_bfloat16 hb = __float2bfloat16(p);
                g_B2h[b * 8192 + o * 32 + hg] = hb;
                g_B2l[b * 8192 + o * 32 + hg] = __float2bfloat16(p - __bfloat162float(hb));
            }
        }
    }
}

// ---------------------------------------------------------------------------
// main kernel v2: 256 positions/block, 256 threads, 2 CTA/SM, grid 256.
// thread = position (LN stats fully private). Warp w owns m-rows [w*32,w*32+32).
// GEMM1 split: xh*wh + xl*wh + xh*wl ; GEMM2 same on attn/P.
// Stores staged through smem -> float4-coalesced.
// smem map (bytes):
//  B1H 0 (32x528)      | later A2H (256x16 u32, XOR-swizzled)
//  B1L 16896 (32x528)  | later A2L
//  B2H 33792 (256x80) | B2L 54272 (256x80)
//  XS 74752: X 2x16640 (16ch x 260f) | S 256x33f (33792) | stage 32x260f
//  CS 108544 | BIAS 108672 | TOT 108800
// ---------------------------------------------------------------------------
#define SB_B1H 0
#define SB_B1L 16896
#define SB_B2H 33792
#define SB_B2L 54272
#define SB_XS  74752
#define SB_CS  108544
#define SB_BIAS 108672
#define SB_TOT 108800

__global__ void __launch_bounds__(256, 2) k_main(
    const float* __restrict__ x2, float* __restrict__ out) {
    extern __shared__ char smc[];
    uint32_t smb = smem_to_u32(smc);
    int tid = threadIdx.x;
    int lane = tid & 31, w = tid >> 5;
    int g = lane >> 2, tg = lane & 3;
    int b = blockIdx.x >> 7;
    int n0 = (blockIdx.x & 127) * 256;
    const float* xb = x2 + (size_t)b * (C * NPOS) + n0;

    // ---- prologue: B operands (group 0), X chunk 0 (group 1), cs/bias
    {
        const char* s1 = (const char*)g_B1h + b * 16384;
        const char* s2 = (const char*)g_B1l + b * 16384;
        for (int i = tid; i < 1024; i += 256) {
            int r = i >> 5, c2 = i & 31;
            cpa16(smb + SB_B1H + r * 528 + c2 * 16, s1 + r * 512 + c2 * 16);
            cpa16(smb + SB_B1L + r * 528 + c2 * 16, s2 + r * 512 + c2 * 16);
        }
        const char* s3 = (const char*)g_B2h + b * 16384;
        const char* s4 = (const char*)g_B2l + b * 16384;
        for (int i = tid; i < 1024; i += 256) {
            int r = i >> 2, c2 = i & 3;
            cpa16(smb + SB_B2H + r * 80 + c2 * 16, s3 + r * 64 + c2 * 16);
            cpa16(smb + SB_B2L + r * 80 + c2 * 16, s4 + r * 64 + c2 * 16);
        }
        cpa_commit();
        for (int i = tid; i < 1024; i += 256) {
            int r = i >> 6, c2 = i & 63;
            cpa16(smb + SB_XS + r * 1040 + c2 * 16, xb + (size_t)r * NPOS + c2 * 4);
        }
        cpa_commit();
        if (tid < 32) ((float*)(smc + SB_CS))[tid] = g_cs[b * 32 + tid];
        else if (tid < 64) ((float*)(smc + SB_BIAS))[tid - 32] = g_bias[b * 32 + tid - 32];
    }

    const uint32_t* b1h = (const uint32_t*)(smc + SB_B1H);
    const uint32_t* b1l = (const uint32_t*)(smc + SB_B1L);
    float d1[2][4][4] = {};
    float s1a = 0.f, s2a = 0.f;
    int k0 = 2 * tg;

    for (int ch = 0; ch < 16; ch++) {
        if (ch < 15) {
            const float* src = xb + (size_t)((ch + 1) * 16) * NPOS;
            unsigned dst = smb + SB_XS + ((unsigned)((ch + 1) & 1)) * 16640u;
            for (int i = tid; i < 1024; i += 256) {
                int r = i >> 6, c2 = i & 63;
                cpa16(dst + r * 1040 + c2 * 16, src + (size_t)r * NPOS + c2 * 4);
            }
            cpa_commit();
            cpa_wait1();
        } else {
            cpa_wait0();
        }
        __syncthreads();
        const float* Xb = (const float*)(smc + SB_XS + ((ch & 1) ? 16640 : 0));

        // LN stats: thread = position, 16 channels of this chunk
#pragma unroll
        for (int i = 0; i < 16; i++) {
            float v = Xb[i * 260 + tid];
            s1a += v; s2a += v * v;
        }

        // A fragments + MMAs for both 16-row m-tiles
#pragma unroll
        for (int t = 0; t < 2; t++) {
            int m0 = w * 32 + t * 16 + g;
            float f[8];
            f[0] = Xb[k0 * 260 + m0];           f[1] = Xb[(k0 + 1) * 260 + m0];
            f[2] = Xb[k0 * 260 + m0 + 8];       f[3] = Xb[(k0 + 1) * 260 + m0 + 8];
            f[4] = Xb[(k0 + 8) * 260 + m0];     f[5] = Xb[(k0 + 9) * 260 + m0];
            f[6] = Xb[(k0 + 8) * 260 + m0 + 8]; f[7] = Xb[(k0 + 9) * 260 + m0 + 8];
            uint32_t ah[4], al[4];
#pragma unroll
            for (int qd = 0; qd < 4; qd++) {
                uint32_t hp = bf16pack(f[2 * qd], f[2 * qd + 1]);
                float r0 = f[2 * qd]     - __uint_as_float(hp << 16);
                float r1 = f[2 * qd + 1] - __uint_as_float(hp & 0xffff0000u);
                ah[qd] = hp;
                al[qd] = bf16pack(r0, r1);
            }
#pragma unroll
            for (int nb = 0; nb < 4; nb++) {
                int n = nb * 8 + g;
                uint32_t bh[2] = { b1h[n * 132 + ch * 8 + tg], b1h[n * 132 + ch * 8 + tg + 4] };
                uint32_t bl[2] = { b1l[n * 132 + ch * 8 + tg], b1l[n * 132 + ch * 8 + tg + 4] };
                mma16816(d1[t][nb], ah, bh);
                mma16816(d1[t][nb], al, bh);
                mma16816(d1[t][nb], ah, bl);
            }
        }
        __syncthreads();
    }

    // ---- D1 -> S (stride-33 rows, overlays X)
    float* S = (float*)(smc + SB_XS);
#pragma unroll
    for (int t = 0; t < 2; t++)
#pragma unroll
        for (int nb = 0; nb < 4; nb++) {
            int m = w * 32 + t * 16 + g;
            int n = nb * 8 + 2 * tg;
            S[m * 33 + n]           = d1[t][nb][0];
            S[m * 33 + n + 1]       = d1[t][nb][1];
            S[(m + 8) * 33 + n]     = d1[t][nb][2];
            S[(m + 8) * 33 + n + 1] = d1[t][nb][3];
        }
    __syncthreads();

    // ---- LN correction + softmax + A2 hi/lo pack (A2 overlays B1; GEMM1 done)
    uint32_t* a2h = (uint32_t*)(smc + SB_B1H);
    uint32_t* a2l = (uint32_t*)(smc + SB_B1L);
    {
        float u = s1a * (1.0f / 256.0f);
        float rstd = rsqrtf(s2a * (1.0f / 256.0f) - u * u + 1e-6f);
        const float* cs = (const float*)(smc + SB_CS);
        const float* bi = (const float*)(smc + SB_BIAS);
        float a[32];
#pragma unroll
        for (int i = 0; i < 32; i++)
            a[i] = (S[tid * 33 + i] - u * cs[i]) * rstd + bi[i];
#pragma unroll
        for (int h = 0; h < 4; h++) {
            float m = -1e30f;
#pragma unroll
            for (int g2 = 0; g2 < 8; g2++) m = fmaxf(m, a[h * 8 + g2]);
            float ssum = 0.f;
#pragma unroll
            for (int g2 = 0; g2 < 8; g2++) { a[h * 8 + g2] = __expf(a[h * 8 + g2] - m); ssum += a[h * 8 + g2]; }
            float inv = 1.0f / ssum;
#pragma unroll
            for (int g2 = 0; g2 < 8; g2++) a[h * 8 + g2] *= inv;
        }
        int sw = tid & 15;
#pragma unroll
        for (int i = 0; i < 16; i++) {
            uint32_t hp = bf16pack(a[2 * i], a[2 * i + 1]);
            float r0 = a[2 * i]     - __uint_as_float(hp << 16);
            float r1 = a[2 * i + 1] - __uint_as_float(hp & 0xffff0000u);
            a2h[tid * 16 + (i ^ sw)] = hp;
            a2l[tid * 16 + (i ^ sw)] = bf16pack(r0, r1);
        }
    }
    __syncthreads();

    // ---- GEMM2 + staged coalesced stores (8 rounds of 32 outputs)
    const uint32_t* b2h = (const uint32_t*)(smc + SB_B2H);
    const uint32_t* b2l = (const uint32_t*)(smc + SB_B2L);
    uint32_t A2H[2][2][4], A2L[2][2][4];
#pragma unroll
    for (int t = 0; t < 2; t++)
#pragma unroll
        for (int kc = 0; kc < 2; kc++) {
            int ma = w * 32 + t * 16 + g, mb = ma + 8;
            int i0 = kc * 8 + tg, i1 = i0 + 4;
            A2H[t][kc][0] = a2h[ma * 16 + (i0 ^ (ma & 15))];
            A2H[t][kc][1] = a2h[mb * 16 + (i0 ^ (mb & 15))];
            A2H[t][kc][2] = a2h[ma * 16 + (i1 ^ (ma & 15))];
            A2H[t][kc][3] = a2h[mb * 16 + (i1 ^ (mb & 15))];
            A2L[t][kc][0] = a2l[ma * 16 + (i0 ^ (ma & 15))];
            A2L[t][kc][1] = a2l[mb * 16 + (i0 ^ (mb & 15))];
            A2L[t][kc][2] = a2l[ma * 16 + (i1 ^ (ma & 15))];
            A2L[t][kc][3] = a2l[mb * 16 + (i1 ^ (mb & 15))];
        }
    float* stg = (float*)(smc + SB_XS);
    float* ob = out + (size_t)b * (C * NPOS) + n0;
    for (int go = 0; go < 8; go++) {
        float d2[2][4][4] = {};
#pragma unroll
        for (int t = 0; t < 2; t++)
#pragma unroll
            for (int nb = 0; nb < 4; nb++) {
                int n = go * 32 + nb * 8 + g;
#pragma unroll
                for (int kc = 0; kc < 2; kc++) {
                    uint32_t bh[2] = { b2h[n * 20 + kc * 8 + tg], b2h[n * 20 + kc * 8 + tg + 4] };
                    uint32_t bl[2] = { b2l[n * 20 + kc * 8 + tg], b2l[n * 20 + kc * 8 + tg + 4] };
                    mma16816(d2[t][nb], A2H[t][kc], bh);
                    mma16816(d2[t][nb], A2L[t][kc], bh);
                    mma16816(d2[t][nb], A2H[t][kc], bl);
                }
            }
        if (go) __syncthreads();   // prior round's stage reads complete
#pragma unroll
        for (int t = 0; t < 2; t++)
#pragma unroll
            for (int nb = 0; nb < 4; nb++) {
                int ol = nb * 8 + 2 * tg;
                int m = w * 32 + t * 16 + g;
                stg[ol * 260 + m]           = d2[t][nb][0];
                stg[(ol + 1) * 260 + m]     = d2[t][nb][1];
                stg[ol * 260 + m + 8]       = d2[t][nb][2];
                stg[(ol + 1) * 260 + m + 8] = d2[t][nb][3];
            }
        __syncthreads();
#pragma unroll
        for (int it = 0; it < 8; it++) {
            int idx = tid + it * 256;
            int row = idx >> 6, c4 = idx & 63;
            float4 v = *reinterpret_cast<const float4*>(stg + row * 260 + c4 * 4);
            *reinterpret_cast<float4*>(ob + (size_t)(go * 32 + row) * NPOS + c4 * 4) = v;
        }
    }
}

// ---------------------------------------------------------------------------
extern "C" void kernel_launch(void* const* d_in, const int* in_sizes, int n_in,
                              void* d_out, int out_size) {
    const float* x2     = (const float*)d_in[0];
    const float* x1_low = (const float*)d_in[1];
    const float* q_w    = (const float*)d_in[2];
    const float* k_w    = (const float*)d_in[3];
    const float* v_w    = (const float*)d_in[4];
    const float* dw_w   = (const float*)d_in[5];
    const float* proj_w = (const float*)d_in[6];
    const float* nq_w   = (const float*)d_in[7];
    const float* nq_b   = (const float*)d_in[8];
    const float* nkv_w  = (const float*)d_in[9];
    const float* nkv_b  = (const float*)d_in[10];
    float* out = (float*)d_out;

    cudaFuncSetAttribute(k_main, cudaFuncAttributeMaxDynamicSharedMemorySize, SB_TOT);

    k_tokens<<<512, 256>>>(x1_low, dw_w);
    k_kv<<<64, 256>>>(k_w, v_w, nkv_w, nkv_b);
    k_fold<<<320, 256>>>(q_w, proj_w, nq_w, nq_b);
    k_main<<<256, 256, SB_TOT>>>(x2, out);
}

// round 12
// speedup vs baseline: 2.1604x; 1.0142x over previous
#include <cuda_runtime.h>
#include <cuda_bf16.h>
#include <cstdint>
#include <math.h>

#define C 256
#define NPOS 32768
#define G 8
#define H 4

// ---- scratch --------------------------------------------------------------
__device__ float g_tokens[2 * C * G];          // [b][c][g]
__device__ float g_K[2 * H * 64 * G];          // [b][h][d][g], pre-scaled by 1/8
__device__ float g_V[2 * H * G * 64];          // [b][h][g][d]
__device__ __nv_bfloat16 g_B1h[2 * 32 * 256];  // [b][hg][c]  Ms~^T hi
__device__ __nv_bfloat16 g_B1l[2 * 32 * 256];  // [b][hg][c]  Ms~^T lo
__device__ __nv_bfloat16 g_B2h[2 * 256 * 32];  // [b][o][hg]  P^T hi
__device__ __nv_bfloat16 g_B2l[2 * 256 * 32];  // [b][o][hg]  P^T lo
__device__ float g_cs[2 * 32];                 // colsum of Ms~
__device__ float g_bias[2 * 32];               // Ms_raw . nq_b

// ---- helpers ----------------------------------------------------------------
__device__ __forceinline__ uint32_t smem_to_u32(const void* p) {
    uint32_t a;
    asm("{ .reg .u64 t; cvta.to.shared.u64 t, %1; cvt.u32.u64 %0, t; }"
        : "=r"(a) : "l"(p));
    return a;
}
__device__ __forceinline__ void cpa16(unsigned s, const void* g) {
    asm volatile("cp.async.cg.shared.global [%0], [%1], 16;" :: "r"(s), "l"(g));
}
__device__ __forceinline__ void cpa_commit() { asm volatile("cp.async.commit_group;"); }
__device__ __forceinline__ void cpa_wait1() { asm volatile("cp.async.wait_group 1;"); }
__device__ __forceinline__ void cpa_wait0() { asm volatile("cp.async.wait_group 0;"); }

// pack two floats into bf16x2: low half = first arg
__device__ __forceinline__ uint32_t bf16pack(float lo, float hi) {
    uint32_t r;
    asm("cvt.rn.bf16x2.f32 %0, %1, %2;" : "=r"(r) : "f"(hi), "f"(lo));
    return r;
}

// D += A(16x16 bf16 row) * B(16x8 bf16 col), fp32 accum
__device__ __forceinline__ void mma16816(float* d, const uint32_t* a, const uint32_t* b) {
    asm volatile(
        "mma.sync.aligned.m16n8k16.row.col.f32.bf16.bf16.f32 "
        "{%0,%1,%2,%3}, {%4,%5,%6,%7}, {%8,%9}, {%0,%1,%2,%3};"
        : "+f"(d[0]), "+f"(d[1]), "+f"(d[2]), "+f"(d[3])
        : "r"(a[0]), "r"(a[1]), "r"(a[2]), "r"(a[3]), "r"(b[0]), "r"(b[1]));
}

// ---------------------------------------------------------------------------
// pool 16^3 -> 2^3 + depthwise 3^3 conv (SAME) + residual
// ---------------------------------------------------------------------------
__global__ void k_tokens(const float* __restrict__ x1,
                         const float* __restrict__ dw_w) {
    int bc = blockIdx.x;
    int c = bc & 255;
    const float* xp = x1 + (size_t)bc * 4096;
    int tid = threadIdx.x;
    int w = tid >> 5, lane = tid & 31;
    int gz = w >> 2, gy = (w >> 1) & 1, gx = w & 1;
    float s = 0.f;
#pragma unroll
    for (int p = 0; p < 2; p++) {
        int idx = lane + p * 32;
        int lz = idx >> 3, ly = idx & 7;
        const float4* r = reinterpret_cast<const float4*>(
            xp + (gz * 8 + lz) * 256 + (gy * 8 + ly) * 16 + gx * 8);
        float4 a = r[0], b4 = r[1];
        s += a.x + a.y + a.z + a.w + b4.x + b4.y + b4.z + b4.w;
    }
#pragma unroll
    for (int off = 16; off; off >>= 1) s += __shfl_down_sync(0xffffffffu, s, off);
    __shared__ float pooled[8];
    if (lane == 0) pooled[w] = s * (1.0f / 512.0f);
    __syncthreads();
    // conv: warp w handles cell w, lane = tap
    int cz = w >> 2, cy = (w >> 1) & 1, cx = w & 1;
    float val = 0.f;
    if (lane < 27) {
        int dz = lane / 9 - 1, dy = (lane / 3) % 3 - 1, dx = lane % 3 - 1;
        int nz = cz + dz, ny = cy + dy, nx = cx + dx;
        if ((unsigned)nz < 2u && (unsigned)ny < 2u && (unsigned)nx < 2u)
            val = dw_w[c * 27 + lane] * pooled[nz * 4 + ny * 2 + nx];
    }
#pragma unroll
    for (int off = 16; off; off >>= 1) val += __shfl_down_sync(0xffffffffu, val, off);
    if (lane == 0) g_tokens[bc * 8 + w] = pooled[w] + val;
}

// ---------------------------------------------------------------------------
// LN(tokens), K (prescaled), V.  grid 64 = (b*8+g)*4 + quarter
// ---------------------------------------------------------------------------
__global__ void k_kv(const float* __restrict__ k_w, const float* __restrict__ v_w,
                     const float* __restrict__ nkv_w, const float* __restrict__ nkv_b) {
    int bid = blockIdx.x;
    int q = bid & 3;
    int bg = bid >> 2;
    int b = bg >> 3, g = bg & 7;
    int tid = threadIdx.x;
    int w = tid >> 5, lane = tid & 31;
    __shared__ float tok[256], tk[256], red[16];
    __shared__ float uu, rstd;
    float t = g_tokens[(b * 256 + tid) * 8 + g];
    tok[tid] = t;
    float s1 = t, s2 = t * t;
#pragma unroll
    for (int off = 16; off; off >>= 1) {
        s1 += __shfl_down_sync(0xffffffffu, s1, off);
        s2 += __shfl_down_sync(0xffffffffu, s2, off);
    }
    if (lane == 0) { red[w] = s1; red[8 + w] = s2; }
    __syncthreads();
    if (tid == 0) {
        float a = 0.f, qq = 0.f;
        for (int i = 0; i < 8; i++) { a += red[i]; qq += red[8 + i]; }
        float u = a * (1.0f / 256.0f);
        float var = qq * (1.0f / 256.0f) - u * u;
        uu = u; rstd = rsqrtf(var + 1e-6f);
    }
    __syncthreads();
    tk[tid] = (t - uu) * rstd * nkv_w[tid] + nkv_b[tid];
    __syncthreads();
#pragma unroll
    for (int oo = 0; oo < 8; oo++) {
        int o = q * 64 + w * 8 + oo;
        const float* kr = k_w + o * 256;
        const float* vr = v_w + o * 256;
        float pk = 0.f, pv = 0.f;
#pragma unroll
        for (int i = 0; i < 8; i++) {
            int c2 = lane + 32 * i;
            pk += kr[c2] * tk[c2];
            pv += vr[c2] * tok[c2];
        }
#pragma unroll
        for (int off = 16; off; off >>= 1) {
            pk += __shfl_down_sync(0xffffffffu, pk, off);
            pv += __shfl_down_sync(0xffffffffu, pv, off);
        }
        if (lane == 0) {
            int h = o >> 6, d = o & 63;
            g_K[((b * 4 + h) * 64 + d) * 8 + g] = pk * 0.125f;
            g_V[((b * 4 + h) * 8 + g) * 64 + d] = pv;
        }
    }
}

// ---------------------------------------------------------------------------
// fused folds. blocks 0..63: B1 = (Ms*nq_w)^T hi/lo + cs/bias (thread = c)
//              blocks 64..319: B2 = P^T hi/lo (warp-per-row quarters)
// ---------------------------------------------------------------------------
__global__ void k_fold(const float* __restrict__ q_w, const float* __restrict__ proj_w,
                       const float* __restrict__ nq_w, const float* __restrict__ nq_b) {
    if (blockIdx.x < 64) {
        int bhg = blockIdx.x;
        int b = bhg >> 5, hg = bhg & 31, h = hg >> 3, g = hg & 7;
        int t = threadIdx.x;
        __shared__ float kd[64];
        __shared__ float r1[8], r2[8];
        if (t < 64) kd[t] = g_K[((b * 4 + h) * 64 + t) * 8 + g];
        __syncthreads();
        float s = 0.f;
        const float* qp = q_w + (h * 64) * 256 + t;
#pragma unroll 8
        for (int d = 0; d < 64; d++) s += qp[d * 256] * kd[d];
        float sp = s * nq_w[t];
        float sb = s * nq_b[t];
        __nv_bfloat16 hb = __float2bfloat16(sp);
        g_B1h[b * 8192 + hg * 256 + t] = hb;
        g_B1l[b * 8192 + hg * 256 + t] = __float2bfloat16(sp - __bfloat162float(hb));
        float a1 = sp, a2 = sb;
#pragma unroll
        for (int off = 16; off; off >>= 1) {
            a1 += __shfl_down_sync(0xffffffffu, a1, off);
            a2 += __shfl_down_sync(0xffffffffu, a2, off);
        }
        int w = t >> 5, lane = t & 31;
        if (lane == 0) { r1[w] = a1; r2[w] = a2; }
        __syncthreads();
        if (t == 0) {
            float c1 = 0.f, c2 = 0.f;
            for (int i = 0; i < 8; i++) { c1 += r1[i]; c2 += r2[i]; }
            g_cs[b * 32 + hg] = c1;
            g_bias[b * 32 + hg] = c2;
        }
    } else {
        int bid = blockIdx.x - 64;
        int q = bid & 3;
        int bhg = bid >> 2;
        int b = bhg >> 5, hg = bhg & 31, h = hg >> 3, g = hg & 7;
        int tid = threadIdx.x;
        int w = tid >> 5, lane = tid & 31;
        __shared__ float vd[64];
        if (tid < 64) vd[tid] = g_V[((b * 4 + h) * 8 + g) * 64 + tid];
        __syncthreads();
#pragma unroll
        for (int oo = 0; oo < 8; oo++) {
            int o = q * 64 + w * 8 + oo;
            const float* pw = proj_w + o * 256 + h * 64;
            float p = pw[lane] * vd[lane] + pw[32 + lane] * vd[32 + lane];
#pragma unroll
            for (int off = 16; off; off >>= 1)
                p += __shfl_down_sync(0xffffffffu, p, off);
            if (lane == 0) {
                __nv_bfloat16 hb = __float2bfloat16(p);
                g_B2h[b * 8192 + o * 32 + hg] = hb;
                g_B2l[b * 8192 + o * 32 + hg] = __float2bfloat16(p - __bfloat162float(hb));
            }
        }
    }
}

// ---------------------------------------------------------------------------
// main kernel v3: 256 positions/block, 256 threads, 2 CTA/SM, grid 256.
// 8 chunks x 32 channels; LN stats folded into the MMA gathers (butterfly).
// smem (bytes), time-multiplexed:
//  R1 = XS 0..66560: X 2x33280 (32ch x 260f) -> B2H@0 (256x80) B2L@20480
//  R2 = 66560..100352: B1H@66560 B1L@83456 -> S(256x33f) -> A2H@66560
//       A2L@82944 -> stage(32x260f)
//  CS 100352 | BIAS 100480 | U 100608 | R 101632 | TOT 102656
// ---------------------------------------------------------------------------
#define SB_XS   0
#define SB_B2H  0
#define SB_B2L  20480
#define SB_R2   66560
#define SB_B1H  66560
#define SB_B1L  83456
#define SB_A2H  66560
#define SB_A2L  82944
#define SB_CS   100352
#define SB_BIAS 100480
#define SB_U    100608
#define SB_R    101632
#define SB_TOT  102656

__global__ void __launch_bounds__(256, 2) k_main(
    const float* __restrict__ x2, float* __restrict__ out) {
    extern __shared__ char smc[];
    uint32_t smb = smem_to_u32(smc);
    int tid = threadIdx.x;
    int lane = tid & 31, w = tid >> 5;
    int g = lane >> 2, tg = lane & 3;
    int b = blockIdx.x >> 7;
    int n0 = (blockIdx.x & 127) * 256;
    const float* xb = x2 + (size_t)b * (C * NPOS) + n0;

    // ---- prologue: B1 (group 0), X chunk 0 (group 1), cs/bias
    {
        const char* s1 = (const char*)g_B1h + b * 16384;
        const char* s2 = (const char*)g_B1l + b * 16384;
        for (int i = tid; i < 1024; i += 256) {
            int r = i >> 5, c2 = i & 31;
            cpa16(smb + SB_B1H + r * 528 + c2 * 16, s1 + r * 512 + c2 * 16);
            cpa16(smb + SB_B1L + r * 528 + c2 * 16, s2 + r * 512 + c2 * 16);
        }
        cpa_commit();
        for (int i = tid; i < 2048; i += 256) {
            int r = i >> 6, c2 = i & 63;
            cpa16(smb + SB_XS + r * 1040 + c2 * 16, xb + (size_t)r * NPOS + c2 * 4);
        }
        cpa_commit();
        if (tid < 32) ((float*)(smc + SB_CS))[tid] = g_cs[b * 32 + tid];
        else if (tid < 64) ((float*)(smc + SB_BIAS))[tid - 32] = g_bias[b * 32 + tid - 32];
    }

    const uint32_t* b1h = (const uint32_t*)(smc + SB_B1H);
    const uint32_t* b1l = (const uint32_t*)(smc + SB_B1L);
    float d1[2][4][4] = {};
    float s1v[2][2] = {}, s2v[2][2] = {};

    for (int ch = 0; ch < 8; ch++) {
        if (ch < 7) {
            const float* src = xb + (size_t)((ch + 1) * 32) * NPOS;
            unsigned dst = smb + SB_XS + ((unsigned)((ch + 1) & 1)) * 33280u;
            for (int i = tid; i < 2048; i += 256) {
                int r = i >> 6, c2 = i & 63;
                cpa16(dst + r * 1040 + c2 * 16, src + (size_t)r * NPOS + c2 * 4);
            }
            cpa_commit();
            cpa_wait1();
        } else {
            cpa_wait0();
        }
        __syncthreads();
        const float* Xb = (const float*)(smc + SB_XS + ((ch & 1) ? 33280 : 0));

#pragma unroll
        for (int t = 0; t < 2; t++) {
            int m0 = w * 32 + t * 16 + g;
#pragma unroll
            for (int kb = 0; kb < 2; kb++) {
                int k0 = kb * 16 + 2 * tg;
                float f[8];
                f[0] = Xb[k0 * 260 + m0];           f[1] = Xb[(k0 + 1) * 260 + m0];
                f[2] = Xb[k0 * 260 + m0 + 8];       f[3] = Xb[(k0 + 1) * 260 + m0 + 8];
                f[4] = Xb[(k0 + 8) * 260 + m0];     f[5] = Xb[(k0 + 9) * 260 + m0];
                f[6] = Xb[(k0 + 8) * 260 + m0 + 8]; f[7] = Xb[(k0 + 9) * 260 + m0 + 8];
                // LN stats folded into gather (each lane-group covers all rows)
                s1v[t][0] += f[0] + f[1] + f[4] + f[5];
                s1v[t][1] += f[2] + f[3] + f[6] + f[7];
                s2v[t][0] += f[0] * f[0] + f[1] * f[1] + f[4] * f[4] + f[5] * f[5];
                s2v[t][1] += f[2] * f[2] + f[3] * f[3] + f[6] * f[6] + f[7] * f[7];
                uint32_t ah[4], al[4];
#pragma unroll
                for (int qd = 0; qd < 4; qd++) {
                    uint32_t hp = bf16pack(f[2 * qd], f[2 * qd + 1]);
                    float r0 = f[2 * qd]     - __uint_as_float(hp << 16);
                    float r1 = f[2 * qd + 1] - __uint_as_float(hp & 0xffff0000u);
                    ah[qd] = hp;
                    al[qd] = bf16pack(r0, r1);
                }
                int kidx = ch * 16 + kb * 8 + tg;
#pragma unroll
                for (int nb = 0; nb < 4; nb++) {
                    int n = nb * 8 + g;
                    uint32_t bh[2] = { b1h[n * 132 + kidx], b1h[n * 132 + kidx + 4] };
                    uint32_t bl[2] = { b1l[n * 132 + kidx], b1l[n * 132 + kidx + 4] };
                    mma16816(d1[t][nb], ah, bh);
                    mma16816(d1[t][nb], al, bh);
                    mma16816(d1[t][nb], ah, bl);
                }
            }
        }
        __syncthreads();   // all warps done with this buffer before next prefetch
    }

    // ---- B2 into dead X region (async, overlapped with epilogue smem work)
    {
        const char* s3 = (const char*)g_B2h + b * 16384;
        const char* s4 = (const char*)g_B2l + b * 16384;
        for (int i = tid; i < 1024; i += 256) {
            int r = i >> 2, c2 = i & 3;
            cpa16(smb + SB_B2H + r * 80 + c2 * 16, s3 + r * 64 + c2 * 16);
            cpa16(smb + SB_B2L + r * 80 + c2 * 16, s4 + r * 64 + c2 * 16);
        }
        cpa_commit();
    }

    // ---- stats butterfly -> U/R (lanes within g-quad hold channel partitions)
    {
#pragma unroll
        for (int t = 0; t < 2; t++)
#pragma unroll
            for (int p = 0; p < 2; p++) {
                s1v[t][p] += __shfl_xor_sync(0xffffffffu, s1v[t][p], 1);
                s1v[t][p] += __shfl_xor_sync(0xffffffffu, s1v[t][p], 2);
                s2v[t][p] += __shfl_xor_sync(0xffffffffu, s2v[t][p], 1);
                s2v[t][p] += __shfl_xor_sync(0xffffffffu, s2v[t][p], 2);
            }
        if (tg == 0) {
            float* U = (float*)(smc + SB_U);
            float* R = (float*)(smc + SB_R);
#pragma unroll
            for (int t = 0; t < 2; t++)
#pragma unroll
                for (int p = 0; p < 2; p++) {
                    int pos = w * 32 + t * 16 + p * 8 + g;
                    float u = s1v[t][p] * (1.0f / 256.0f);
                    U[pos] = u;
                    R[pos] = rsqrtf(s2v[t][p] * (1.0f / 256.0f) - u * u + 1e-6f);
                }
        }
    }

    // ---- D1 -> S (R2 region; B1 dead after GEMM1)
    float* S = (float*)(smc + SB_R2);
#pragma unroll
    for (int t = 0; t < 2; t++)
#pragma unroll
        for (int nb = 0; nb < 4; nb++) {
            int m = w * 32 + t * 16 + g;
            int n = nb * 8 + 2 * tg;
            S[m * 33 + n]           = d1[t][nb][0];
            S[m * 33 + n + 1]       = d1[t][nb][1];
            S[(m + 8) * 33 + n]     = d1[t][nb][2];
            S[(m + 8) * 33 + n + 1] = d1[t][nb][3];
        }
    __syncthreads();

    // ---- LN correction + softmax (thread = position; a[] in regs)
    float a[32];
    {
        float u = ((const float*)(smc + SB_U))[tid];
        float rstd = ((const float*)(smc + SB_R))[tid];
        const float* cs = (const float*)(smc + SB_CS);
        const float* bi = (const float*)(smc + SB_BIAS);
#pragma unroll
        for (int i = 0; i < 32; i++)
            a[i] = (S[tid * 33 + i] - u * cs[i]) * rstd + bi[i];
#pragma unroll
        for (int h = 0; h < 4; h++) {
            float m = -1e30f;
#pragma unroll
            for (int g2 = 0; g2 < 8; g2++) m = fmaxf(m, a[h * 8 + g2]);
            float ssum = 0.f;
#pragma unroll
            for (int g2 = 0; g2 < 8; g2++) { a[h * 8 + g2] = __expf(a[h * 8 + g2] - m); ssum += a[h * 8 + g2]; }
            float inv = 1.0f / ssum;
#pragma unroll
            for (int g2 = 0; g2 < 8; g2++) a[h * 8 + g2] *= inv;
        }
    }
    __syncthreads();       // all S reads complete before A2 overlays it

    // ---- A2 hi/lo pack into R2 (XOR-swizzled)
    uint32_t* a2h = (uint32_t*)(smc + SB_A2H);
    uint32_t* a2l = (uint32_t*)(smc + SB_A2L);
    {
        int sw = tid & 15;
#pragma unroll
        for (int i = 0; i < 16; i++) {
            uint32_t hp = bf16pack(a[2 * i], a[2 * i + 1]);
            float r0 = a[2 * i]     - __uint_as_float(hp << 16);
            float r1 = a[2 * i + 1] - __uint_as_float(hp & 0xffff0000u);
            a2h[tid * 16 + (i ^ sw)] = hp;
            a2l[tid * 16 + (i ^ sw)] = bf16pack(r0, r1);
        }
    }
    __syncthreads();

    // ---- A2 fragments -> regs
    uint32_t A2H[2][2][4], A2L[2][2][4];
#pragma unroll
    for (int t = 0; t < 2; t++)
#pragma unroll
        for (int kc = 0; kc < 2; kc++) {
            int ma = w * 32 + t * 16 + g, mb = ma + 8;
            int i0 = kc * 8 + tg, i1 = i0 + 4;
            A2H[t][kc][0] = a2h[ma * 16 + (i0 ^ (ma & 15))];
            A2H[t][kc][1] = a2h[mb * 16 + (i0 ^ (mb & 15))];
            A2H[t][kc][2] = a2h[ma * 16 + (i1 ^ (ma & 15))];
            A2H[t][kc][3] = a2h[mb * 16 + (i1 ^ (mb & 15))];
            A2L[t][kc][0] = a2l[ma * 16 + (i0 ^ (ma & 15))];
            A2L[t][kc][1] = a2l[mb * 16 + (i0 ^ (mb & 15))];
            A2L[t][kc][2] = a2l[ma * 16 + (i1 ^ (ma & 15))];
            A2L[t][kc][3] = a2l[mb * 16 + (i1 ^ (mb & 15))];
        }
    cpa_wait0();           // B2 resident
    __syncthreads();       // A2 reads done (R2 free for stage) + B2 visible

    // ---- GEMM2 + staged coalesced stores (8 rounds of 32 outputs)
    const uint32_t* b2h = (const uint32_t*)(smc + SB_B2H);
    const uint32_t* b2l = (const uint32_t*)(smc + SB_B2L);
    float* stg = (float*)(smc + SB_R2);
    float* ob = out + (size_t)b * (C * NPOS) + n0;
    for (int go = 0; go < 8; go++) {
        float d2[2][4][4] = {};
#pragma unroll
        for (int t = 0; t < 2; t++)
#pragma unroll
            for (int nb = 0; nb < 4; nb++) {
                int n = go * 32 + nb * 8 + g;
#pragma unroll
                for (int kc = 0; kc < 2; kc++) {
                    uint32_t bh[2] = { b2h[n * 20 + kc * 8 + tg], b2h[n * 20 + kc * 8 + tg + 4] };
                    uint32_t bl[2] = { b2l[n * 20 + kc * 8 + tg], b2l[n * 20 + kc * 8 + tg + 4] };
                    mma16816(d2[t][nb], A2H[t][kc], bh);
                    mma16816(d2[t][nb], A2L[t][kc], bh);
                    mma16816(d2[t][nb], A2H[t][kc], bl);
                }
            }
        if (go) __syncthreads();   // prior round's stage reads complete
#pragma unroll
        for (int t = 0; t < 2; t++)
#pragma unroll
            for (int nb = 0; nb < 4; nb++) {
                int ol = nb * 8 + 2 * tg;
                int m = w * 32 + t * 16 + g;
                stg[ol * 260 + m]           = d2[t][nb][0];
                stg[(ol + 1) * 260 + m]     = d2[t][nb][1];
                stg[ol * 260 + m + 8]       = d2[t][nb][2];
                stg[(ol + 1) * 260 + m + 8] = d2[t][nb][3];
            }
        __syncthreads();
#pragma unroll
        for (int it = 0; it < 8; it++) {
            int idx = tid + it * 256;
            int row = idx >> 6, c4 = idx & 63;
            float4 v = *reinterpret_cast<const float4*>(stg + row * 260 + c4 * 4);
            *reinterpret_cast<float4*>(ob + (size_t)(go * 32 + row) * NPOS + c4 * 4) = v;
        }
    }
}

// ---------------------------------------------------------------------------
extern "C" void kernel_launch(void* const* d_in, const int* in_sizes, int n_in,
                              void* d_out, int out_size) {
    const float* x2     = (const float*)d_in[0];
    const float* x1_low = (const float*)d_in[1];
    const float* q_w    = (const float*)d_in[2];
    const float* k_w    = (const float*)d_in[3];
    const float* v_w    = (const float*)d_in[4];
    const float* dw_w   = (const float*)d_in[5];
    const float* proj_w = (const float*)d_in[6];
    const float* nq_w   = (const float*)d_in[7];
    const float* nq_b   = (const float*)d_in[8];
    const float* nkv_w  = (const float*)d_in[9];
    const float* nkv_b  = (const float*)d_in[10];
    float* out = (float*)d_out;

    cudaFuncSetAttribute(k_main, cudaFuncAttributeMaxDynamicSharedMemorySize, SB_TOT);

    k_tokens<<<512, 256>>>(x1_low, dw_w);
    k_kv<<<64, 256>>>(k_w, v_w, nkv_w, nkv_b);
    k_fold<<<320, 256>>>(q_w, proj_w, nq_w, nq_b);
    k_main<<<256, 256, SB_TOT>>>(x2, out);
}